// round 11
// baseline (speedup 1.0000x reference)
#include <cuda_runtime.h>
#include <math.h>
#include <stdint.h>

#define S_TOK 4096
#define MDIM  1024
#define NEXP  8
#define CAP   1024
#define NSLOT (NEXP*CAP)        // 8192
#define GATE_BLOCKS (S_TOK/8)   // 512

// ---------------- device scratch (no allocations allowed) ----------------
__device__ int   g_e1[S_TOK], g_e2[S_TOK];
__device__ float g_p1[S_TOK], g_p2[S_TOK];
__device__ float g_w1[S_TOK], g_w2[S_TOK];
__device__ int   g_slot1[S_TOK], g_slot2[S_TOK];
__device__ int   g_slot2tok[NSLOT];
__device__ float g_me_part[GATE_BLOCKS*NEXP];
__device__ int   g_ce_part[GATE_BLOCKS*NEXP];
__device__ float g_eout[(size_t)NSLOT*MDIM];     // 32 MB (expert outputs)

// ---------------- helpers ----------------
__device__ __forceinline__ uint32_t smem_u32(const void* p) {
    uint32_t a;
    asm("{ .reg .u64 t; cvta.to.shared.u64 t, %1; cvt.u32.u64 %0, t; }" : "=r"(a) : "l"(p));
    return a;
}
__device__ __forceinline__ uint32_t tf32_bits(float v) {
    float r;
    asm("cvt.rna.tf32.f32 %0, %1;" : "=f"(r) : "f"(v));
    return __float_as_uint(r);
}
__device__ __forceinline__ void mma_tf32(float* d, const uint32_t* a, const uint32_t* b) {
    asm volatile(
        "mma.sync.aligned.m16n8k8.row.col.f32.tf32.tf32.f32 "
        "{%0,%1,%2,%3}, {%4,%5,%6,%7}, {%8,%9}, {%0,%1,%2,%3};"
        : "+f"(d[0]), "+f"(d[1]), "+f"(d[2]), "+f"(d[3])
        : "r"(a[0]), "r"(a[1]), "r"(a[2]), "r"(a[3]), "r"(b[0]), "r"(b[1]));
}
#define CP_ASYNC16(dst, src) \
    asm volatile("cp.async.cg.shared.global [%0], [%1], 16;" :: "r"(dst), "l"(src))
#define CP_ASYNC16Z(dst, src, sz) \
    asm volatile("cp.async.cg.shared.global [%0], [%1], 16, %2;" :: "r"(dst), "l"(src), "r"(sz))
#define CP_COMMIT() asm volatile("cp.async.commit_group;" ::: "memory")
#define CP_WAIT3()  asm volatile("cp.async.wait_group 3;" ::: "memory")

// ---------------- gating (+ fused init of slot map) ----------------
__global__ void k_gate(const float* __restrict__ x, const float* __restrict__ wg) {
    // fused init: slot->token map (completes before k_scan in stream order)
    if (threadIdx.x < 16) g_slot2tok[blockIdx.x * 16 + threadIdx.x] = -1;

    int warp = threadIdx.x >> 5, lane = threadIdx.x & 31;
    int s = blockIdx.x * 8 + warp;

    float acc[NEXP];
#pragma unroll
    for (int e = 0; e < NEXP; e++) acc[e] = 0.f;

    const float* xr = x + (size_t)s * MDIM;
    for (int m = lane; m < MDIM; m += 32) {
        float xv = xr[m];
        const float4* w4 = (const float4*)(wg + (size_t)m * NEXP);
        float4 w0 = w4[0], w1 = w4[1];
        acc[0] += xv * w0.x; acc[1] += xv * w0.y;
        acc[2] += xv * w0.z; acc[3] += xv * w0.w;
        acc[4] += xv * w1.x; acc[5] += xv * w1.y;
        acc[6] += xv * w1.z; acc[7] += xv * w1.w;
    }
#pragma unroll
    for (int o = 16; o > 0; o >>= 1) {
#pragma unroll
        for (int e = 0; e < NEXP; e++)
            acc[e] += __shfl_down_sync(0xFFFFFFFFu, acc[e], o);
    }

    __shared__ float sh_g[8][NEXP];
    __shared__ int   sh_e1[8];

    if (lane == 0) {
        float mx = acc[0];
#pragma unroll
        for (int e = 1; e < NEXP; e++) mx = fmaxf(mx, acc[e]);
        float ex[NEXP]; float sum = 0.f;
#pragma unroll
        for (int e = 0; e < NEXP; e++) { ex[e] = expf(acc[e] - mx); sum += ex[e]; }
        float inv = 1.f / sum;

        int e1 = 0; float b1 = acc[0];
#pragma unroll
        for (int e = 1; e < NEXP; e++) if (acc[e] > b1) { b1 = acc[e]; e1 = e; }
        int e2 = -1; float b2 = -3.4e38f;
#pragma unroll
        for (int e = 0; e < NEXP; e++) if (e != e1 && acc[e] > b2) { b2 = acc[e]; e2 = e; }

        float p1 = 0.f, p2 = 0.f;
#pragma unroll
        for (int e = 0; e < NEXP; e++) {
            float ge = ex[e] * inv;
            if (e == e1) p1 = ge;
            if (e == e2) p2 = ge;
            sh_g[warp][e] = ge;
        }
        g_e1[s] = e1; g_e2[s] = e2;
        g_p1[s] = p1; g_p2[s] = p2;
        sh_e1[warp] = e1;
    }
    __syncthreads();

    if (threadIdx.x < NEXP) {
        int e = threadIdx.x;
        float ms = 0.f; int cs = 0;
#pragma unroll
        for (int w = 0; w < 8; w++) { ms += sh_g[w][e]; cs += (sh_e1[w] == e); }
        g_me_part[blockIdx.x * NEXP + e] = ms;
        g_ce_part[blockIdx.x * NEXP + e] = cs;
    }
}

// ---------------- scan (512 threads) ----------------
#define SCAN_T 512
__global__ void k_scan(float* __restrict__ out, int out_size) {
    const int T = SCAN_T, PT = S_TOK / T;   // 8 tokens per thread
    int tid = threadIdx.x;

    __shared__ int   sc1[T][NEXP], sc2[T][NEXP];
    __shared__ float sh_me[NEXP];
    __shared__ int   sh_ce[NEXP];
    __shared__ int   tot1[NEXP];

    if (tid < NEXP) {
        float ms = 0.f; int cs = 0;
        for (int b = 0; b < GATE_BLOCKS; b++) {
            ms += g_me_part[b * NEXP + tid];
            cs += g_ce_part[b * NEXP + tid];
        }
        sh_me[tid] = ms; sh_ce[tid] = cs;
    }

    int c1[NEXP], c2[NEXP];
#pragma unroll
    for (int e = 0; e < NEXP; e++) { c1[e] = 0; c2[e] = 0; }
    for (int i = 0; i < PT; i++) {
        int s = tid * PT + i;
        c1[g_e1[s]]++;
        c2[g_e2[s]]++;
    }
#pragma unroll
    for (int e = 0; e < NEXP; e++) { sc1[tid][e] = c1[e]; sc2[tid][e] = c2[e]; }
    __syncthreads();

    for (int off = 1; off < T; off *= 2) {
        int v1[NEXP], v2[NEXP];
        if (tid >= off) {
#pragma unroll
            for (int e = 0; e < NEXP; e++) { v1[e] = sc1[tid - off][e]; v2[e] = sc2[tid - off][e]; }
        }
        __syncthreads();
        if (tid >= off) {
#pragma unroll
            for (int e = 0; e < NEXP; e++) { sc1[tid][e] += v1[e]; sc2[tid][e] += v2[e]; }
        }
        __syncthreads();
    }
    if (tid < NEXP) tot1[tid] = sc1[T - 1][tid];

    int b1[NEXP], b2[NEXP];
#pragma unroll
    for (int e = 0; e < NEXP; e++) { b1[e] = sc1[tid][e] - c1[e]; b2[e] = sc2[tid][e] - c2[e]; }
    __syncthreads();

    for (int i = 0; i < PT; i++) {
        int s = tid * PT + i;
        int e1 = g_e1[s], e2 = g_e2[s];
        int loc1 = b1[e1]++;
        int loc2 = b2[e2]++ + tot1[e2];
        float p1 = g_p1[s], p2 = g_p2[s];
        bool k1 = (loc1 < CAP), k2 = (loc2 < CAP);
        float gg1 = k1 ? p1 : 0.f, gg2 = k2 ? p2 : 0.f;
        float den = gg1 + gg2;
        den = fmaxf(den, 1.1920929e-07f);
        g_w1[s] = gg1 / den;
        g_w2[s] = gg2 / den;
        int sl1 = k1 ? (e1 * CAP + loc1) : -1;
        int sl2 = k2 ? (e2 * CAP + loc2) : -1;
        g_slot1[s] = sl1; g_slot2[s] = sl2;
        if (sl1 >= 0) g_slot2tok[sl1] = s;
        if (sl2 >= 0) g_slot2tok[sl2] = s;
    }

    if (tid == 0 && out_size > S_TOK * MDIM) {
        float la = 0.f;
#pragma unroll
        for (int e = 0; e < NEXP; e++)
            la += (sh_me[e] / (float)S_TOK) * ((float)sh_ce[e] / (float)S_TOK);
        out[(size_t)S_TOK * MDIM] = la * (float)NEXP;
    }
}

// ---------------- tensor-core GEMM: 4-stage pipeline, fused indirect A gather ----------------
// CTA tile 128x128x16, 8 warps (warp tile 32x64), 4-stage circular cp.async
#define BM 128
#define BN 128
#define BK 16
#define NSTG (MDIM / BK)            // 64
#define NPIPE 4
#define ASTRIDE 20                  // 16 + 4 pad (conflict-free, 16B-aligned chunks)
#define BSTRIDE 136                 // 128 + 8 pad (conflict-free)
#define ABUF (BM * ASTRIDE)         // 2560 floats
#define BBUF (BK * BSTRIDE)         // 2176 floats
#define BUFSZ (ABUF + BBUF)         // 4736 floats
#define GEMM_SMEM (NPIPE * BUFSZ * 4)   // 75776 bytes (dynamic)

__global__ void __launch_bounds__(256, 2) k_gemm_mma(const float* __restrict__ x,
                                                     const float* __restrict__ W,
                                                     const float* __restrict__ bias) {
    extern __shared__ float smf[];
    int tid = threadIdx.x, wid = tid >> 5, lane = tid & 31;
    int grp = lane >> 2, tg = lane & 3;
    int e = blockIdx.z;
    int row0 = blockIdx.y * BM;
    int col0 = blockIdx.x * BN;
    const float* Bg = W + (size_t)e * MDIM * MDIM + col0;
    int wm = (wid & 3) * 32, wn = (wid >> 2) * 64;

    // indirect A-gather: this thread's two A rows -> token sources
    int arow = tid >> 2, aq = tid & 3;     // A rows arow, arow+64 ; 16B chunk aq
    int brow = tid >> 5, bq = tid & 31;    // B k-rows brow, brow+8 ; 16B chunk bq
    int slotbase = e * CAP + row0;
    int t0 = g_slot2tok[slotbase + arow];
    int t1 = g_slot2tok[slotbase + arow + 64];
    const float* a0src = x + (size_t)(t0 < 0 ? 0 : t0) * MDIM + aq * 4;
    const float* a1src = x + (size_t)(t1 < 0 ? 0 : t1) * MDIM + aq * 4;
    uint32_t a0sz = (t0 >= 0) ? 16u : 0u;
    uint32_t a1sz = (t1 >= 0) ? 16u : 0u;
    uint32_t s0 = smem_u32(smf);

    // bias segments for this thread's output columns
    float2 bb[8];
#pragma unroll
    for (int nj = 0; nj < 8; nj++)
        bb[nj] = *(const float2*)(bias + (size_t)e * MDIM + col0 + wn + nj * 8 + tg * 2);

    float d[2][8][4];
#pragma unroll
    for (int mi = 0; mi < 2; mi++)
#pragma unroll
        for (int nj = 0; nj < 8; nj++)
#pragma unroll
            for (int q = 0; q < 4; q++) d[mi][nj][q] = 0.f;

#define LOAD_STAGE(buf, k0) do {                                                       \
    uint32_t sa = s0 + (uint32_t)((buf) * BUFSZ) * 4u;                                 \
    uint32_t sb_ = sa + ABUF * 4u;                                                     \
    CP_ASYNC16Z(sa + (uint32_t)(arow * ASTRIDE + aq * 4) * 4u, a0src + (k0), a0sz);    \
    CP_ASYNC16Z(sa + (uint32_t)((arow + 64) * ASTRIDE + aq * 4) * 4u, a1src + (k0), a1sz); \
    CP_ASYNC16(sb_ + (uint32_t)(brow * BSTRIDE + bq * 4) * 4u,                         \
               Bg + (size_t)((k0) + brow) * MDIM + bq * 4);                            \
    CP_ASYNC16(sb_ + (uint32_t)((brow + 8) * BSTRIDE + bq * 4) * 4u,                   \
               Bg + (size_t)((k0) + brow + 8) * MDIM + bq * 4);                        \
} while (0)

    // prologue: prefetch stages 0..2 (3 groups in flight)
#pragma unroll
    for (int p = 0; p < NPIPE - 1; p++) {
        LOAD_STAGE(p, p * BK);
        CP_COMMIT();
    }

    for (int s = 0; s < NSTG; s++) {
        int cur = s & (NPIPE - 1);
        // issue load for stage s+3 (into buffer freed at end of stage s-1)
        if (s + NPIPE - 1 < NSTG)
            LOAD_STAGE((s + NPIPE - 1) & (NPIPE - 1), (s + NPIPE - 1) * BK);
        CP_COMMIT();               // one group per iteration (possibly empty)
        CP_WAIT3();                // ≤3 pending → group for stage s retired
        __syncthreads();

        const float* As = smf + cur * BUFSZ;
        const float* Bs = As + ABUF;
#pragma unroll
        for (int ks = 0; ks < 2; ks++) {
            int kb = ks * 8;
            uint32_t a[2][4];
#pragma unroll
            for (int mi = 0; mi < 2; mi++) {
                const float* ap = As + (wm + mi * 16 + grp) * ASTRIDE + kb + tg;
                a[mi][0] = tf32_bits(ap[0]);
                a[mi][1] = tf32_bits(ap[8 * ASTRIDE]);
                a[mi][2] = tf32_bits(ap[4]);
                a[mi][3] = tf32_bits(ap[8 * ASTRIDE + 4]);
            }
            uint32_t b[8][2];
#pragma unroll
            for (int nj = 0; nj < 8; nj++) {
                const float* bp = Bs + (kb + tg) * BSTRIDE + wn + nj * 8 + grp;
                b[nj][0] = tf32_bits(bp[0]);
                b[nj][1] = tf32_bits(bp[4 * BSTRIDE]);
            }
#pragma unroll
            for (int mi = 0; mi < 2; mi++)
#pragma unroll
                for (int nj = 0; nj < 8; nj++)
                    mma_tf32(d[mi][nj], a[mi], b[nj]);
        }
        __syncthreads();
    }

    // epilogue: write 32x64 warp tile + bias
    float* Cp = g_eout + (size_t)e * CAP * MDIM;
#pragma unroll
    for (int mi = 0; mi < 2; mi++) {
        int row = row0 + wm + mi * 16 + grp;
#pragma unroll
        for (int nj = 0; nj < 8; nj++) {
            int col = col0 + wn + nj * 8 + tg * 2;
            float2 v0, v1;
            v0.x = d[mi][nj][0] + bb[nj].x;
            v0.y = d[mi][nj][1] + bb[nj].y;
            v1.x = d[mi][nj][2] + bb[nj].x;
            v1.y = d[mi][nj][3] + bb[nj].y;
            *(float2*)(Cp + (size_t)row * MDIM + col) = v0;
            *(float2*)(Cp + (size_t)(row + 8) * MDIM + col) = v1;
        }
    }
}

// ---------------- combine ----------------
__global__ void k_combine(float* __restrict__ out) {
    int s = blockIdx.x;
    float w1 = g_w1[s], w2 = g_w2[s];
    int sl1 = g_slot1[s], sl2 = g_slot2[s];
    int i = threadIdx.x;
    float4 r = make_float4(0.f, 0.f, 0.f, 0.f);
    if (sl1 >= 0) {
        float4 v = ((const float4*)(g_eout + (size_t)sl1 * MDIM))[i];
        r.x += w1 * v.x; r.y += w1 * v.y; r.z += w1 * v.z; r.w += w1 * v.w;
    }
    if (sl2 >= 0) {
        float4 v = ((const float4*)(g_eout + (size_t)sl2 * MDIM))[i];
        r.x += w2 * v.x; r.y += w2 * v.y; r.z += w2 * v.z; r.w += w2 * v.w;
    }
    ((float4*)(out + (size_t)s * MDIM))[i] = r;
}

// ---------------- launch ----------------
extern "C" void kernel_launch(void* const* d_in, const int* in_sizes, int n_in,
                              void* d_out, int out_size) {
    const float* x  = (const float*)d_in[0];   // [2,2048,1024]
    const float* wg = (const float*)d_in[1];   // [1024,8]
    const float* ew = (const float*)d_in[2];   // [8,1024,1024]
    const float* eb = (const float*)d_in[3];   // [8,1024]
    float* out = (float*)d_out;

    cudaFuncSetAttribute(k_gemm_mma, cudaFuncAttributeMaxDynamicSharedMemorySize, GEMM_SMEM);

    k_gate<<<GATE_BLOCKS, 256>>>(x, wg);
    k_scan<<<1, SCAN_T>>>(out, out_size);
    dim3 gg(MDIM / BN, CAP / BM, NEXP);   // 8 x 8 x 8
    k_gemm_mma<<<gg, 256, GEMM_SMEM>>>(x, ew, eb);
    k_combine<<<S_TOK, 256>>>(out);
}

// round 12
// speedup vs baseline: 1.1492x; 1.1492x over previous
#include <cuda_runtime.h>
#include <cuda_fp16.h>
#include <math.h>
#include <stdint.h>

#define S_TOK 4096
#define MDIM  1024
#define NEXP  8
#define CAP   1024
#define NSLOT (NEXP*CAP)        // 8192
#define GATE_BLOCKS (S_TOK/8)   // 512

// ---------------- device scratch (no allocations allowed) ----------------
__device__ int    g_e1[S_TOK], g_e2[S_TOK];
__device__ float  g_p1[S_TOK], g_p2[S_TOK];
__device__ float  g_w1[S_TOK], g_w2[S_TOK];
__device__ int    g_slot1[S_TOK], g_slot2[S_TOK];
__device__ int    g_slot2tok[NSLOT];
__device__ float  g_me_part[GATE_BLOCKS*NEXP];
__device__ int    g_ce_part[GATE_BLOCKS*NEXP];
__device__ float  g_eout[(size_t)NSLOT*MDIM];       // 32 MB (expert outputs)
__device__ __half g_xh[(size_t)S_TOK*MDIM];         // 8 MB  (x in fp16)
__device__ __half g_wh[(size_t)NEXP*MDIM*MDIM];     // 16 MB (W transposed [e][n][k] fp16)

// ---------------- helpers ----------------
__device__ __forceinline__ uint32_t smem_u32(const void* p) {
    uint32_t a;
    asm("{ .reg .u64 t; cvta.to.shared.u64 t, %1; cvt.u32.u64 %0, t; }" : "=r"(a) : "l"(p));
    return a;
}
__device__ __forceinline__ void mma_f16(float* d, const uint32_t* a, const uint32_t* b) {
    asm volatile(
        "mma.sync.aligned.m16n8k16.row.col.f32.f16.f16.f32 "
        "{%0,%1,%2,%3}, {%4,%5,%6,%7}, {%8,%9}, {%0,%1,%2,%3};"
        : "+f"(d[0]), "+f"(d[1]), "+f"(d[2]), "+f"(d[3])
        : "r"(a[0]), "r"(a[1]), "r"(a[2]), "r"(a[3]), "r"(b[0]), "r"(b[1]));
}
#define CP_ASYNC16(dst, src) \
    asm volatile("cp.async.cg.shared.global [%0], [%1], 16;" :: "r"(dst), "l"(src))
#define CP_ASYNC16Z(dst, src, sz) \
    asm volatile("cp.async.cg.shared.global [%0], [%1], 16, %2;" :: "r"(dst), "l"(src), "r"(sz))
#define CP_COMMIT() asm volatile("cp.async.commit_group;" ::: "memory")
#define CP_WAIT3()  asm volatile("cp.async.wait_group 3;" ::: "memory")

// ---------------- gating (+ fused slot-map init + fused x->fp16 convert) ----------------
__global__ void k_gate(const float* __restrict__ x, const float* __restrict__ wg) {
    if (threadIdx.x < 16) g_slot2tok[blockIdx.x * 16 + threadIdx.x] = -1;

    int warp = threadIdx.x >> 5, lane = threadIdx.x & 31;
    int s = blockIdx.x * 8 + warp;

    float acc[NEXP];
#pragma unroll
    for (int e = 0; e < NEXP; e++) acc[e] = 0.f;

    const float* xr = x + (size_t)s * MDIM;
    __half* xh = g_xh + (size_t)s * MDIM;
    for (int m = lane; m < MDIM; m += 32) {
        float xv = xr[m];
        xh[m] = __float2half_rn(xv);          // fused fp16 conversion
        const float4* w4 = (const float4*)(wg + (size_t)m * NEXP);
        float4 w0 = w4[0], w1 = w4[1];
        acc[0] += xv * w0.x; acc[1] += xv * w0.y;
        acc[2] += xv * w0.z; acc[3] += xv * w0.w;
        acc[4] += xv * w1.x; acc[5] += xv * w1.y;
        acc[6] += xv * w1.z; acc[7] += xv * w1.w;
    }
#pragma unroll
    for (int o = 16; o > 0; o >>= 1) {
#pragma unroll
        for (int e = 0; e < NEXP; e++)
            acc[e] += __shfl_down_sync(0xFFFFFFFFu, acc[e], o);
    }

    __shared__ float sh_g[8][NEXP];
    __shared__ int   sh_e1[8];

    if (lane == 0) {
        float mx = acc[0];
#pragma unroll
        for (int e = 1; e < NEXP; e++) mx = fmaxf(mx, acc[e]);
        float ex[NEXP]; float sum = 0.f;
#pragma unroll
        for (int e = 0; e < NEXP; e++) { ex[e] = expf(acc[e] - mx); sum += ex[e]; }
        float inv = 1.f / sum;

        int e1 = 0; float b1 = acc[0];
#pragma unroll
        for (int e = 1; e < NEXP; e++) if (acc[e] > b1) { b1 = acc[e]; e1 = e; }
        int e2 = -1; float b2 = -3.4e38f;
#pragma unroll
        for (int e = 0; e < NEXP; e++) if (e != e1 && acc[e] > b2) { b2 = acc[e]; e2 = e; }

        float p1 = 0.f, p2 = 0.f;
#pragma unroll
        for (int e = 0; e < NEXP; e++) {
            float ge = ex[e] * inv;
            if (e == e1) p1 = ge;
            if (e == e2) p2 = ge;
            sh_g[warp][e] = ge;
        }
        g_e1[s] = e1; g_e2[s] = e2;
        g_p1[s] = p1; g_p2[s] = p2;
        sh_e1[warp] = e1;
    }
    __syncthreads();

    if (threadIdx.x < NEXP) {
        int e = threadIdx.x;
        float ms = 0.f; int cs = 0;
#pragma unroll
        for (int w = 0; w < 8; w++) { ms += sh_g[w][e]; cs += (sh_e1[w] == e); }
        g_me_part[blockIdx.x * NEXP + e] = ms;
        g_ce_part[blockIdx.x * NEXP + e] = cs;
    }
}

// ---------------- W transpose + fp16 convert: [e][k][n] -> [e][n][k] ----------------
__global__ void k_wh(const float* __restrict__ W) {
    __shared__ float t[32][33];
    int e = blockIdx.z;
    int n0 = blockIdx.x * 32, k0 = blockIdx.y * 32;
    const float* src = W + (size_t)e * MDIM * MDIM;
    __half* dst = g_wh + (size_t)e * MDIM * MDIM;
    int tx = threadIdx.x, ty = threadIdx.y;   // 32 x 8
#pragma unroll
    for (int i = 0; i < 32; i += 8)
        t[ty + i][tx] = src[(size_t)(k0 + ty + i) * MDIM + n0 + tx];
    __syncthreads();
#pragma unroll
    for (int i = 0; i < 32; i += 8)
        dst[(size_t)(n0 + ty + i) * MDIM + k0 + tx] = __float2half_rn(t[tx][ty + i]);
}

// ---------------- scan (512 threads) ----------------
#define SCAN_T 512
__global__ void k_scan(float* __restrict__ out, int out_size) {
    const int T = SCAN_T, PT = S_TOK / T;
    int tid = threadIdx.x;

    __shared__ int   sc1[T][NEXP], sc2[T][NEXP];
    __shared__ float sh_me[NEXP];
    __shared__ int   sh_ce[NEXP];
    __shared__ int   tot1[NEXP];

    if (tid < NEXP) {
        float ms = 0.f; int cs = 0;
        for (int b = 0; b < GATE_BLOCKS; b++) {
            ms += g_me_part[b * NEXP + tid];
            cs += g_ce_part[b * NEXP + tid];
        }
        sh_me[tid] = ms; sh_ce[tid] = cs;
    }

    int c1[NEXP], c2[NEXP];
#pragma unroll
    for (int e = 0; e < NEXP; e++) { c1[e] = 0; c2[e] = 0; }
    for (int i = 0; i < PT; i++) {
        int s = tid * PT + i;
        c1[g_e1[s]]++;
        c2[g_e2[s]]++;
    }
#pragma unroll
    for (int e = 0; e < NEXP; e++) { sc1[tid][e] = c1[e]; sc2[tid][e] = c2[e]; }
    __syncthreads();

    for (int off = 1; off < T; off *= 2) {
        int v1[NEXP], v2[NEXP];
        if (tid >= off) {
#pragma unroll
            for (int e = 0; e < NEXP; e++) { v1[e] = sc1[tid - off][e]; v2[e] = sc2[tid - off][e]; }
        }
        __syncthreads();
        if (tid >= off) {
#pragma unroll
            for (int e = 0; e < NEXP; e++) { sc1[tid][e] += v1[e]; sc2[tid][e] += v2[e]; }
        }
        __syncthreads();
    }
    if (tid < NEXP) tot1[tid] = sc1[T - 1][tid];

    int b1[NEXP], b2[NEXP];
#pragma unroll
    for (int e = 0; e < NEXP; e++) { b1[e] = sc1[tid][e] - c1[e]; b2[e] = sc2[tid][e] - c2[e]; }
    __syncthreads();

    for (int i = 0; i < PT; i++) {
        int s = tid * PT + i;
        int e1 = g_e1[s], e2 = g_e2[s];
        int loc1 = b1[e1]++;
        int loc2 = b2[e2]++ + tot1[e2];
        float p1 = g_p1[s], p2 = g_p2[s];
        bool k1 = (loc1 < CAP), k2 = (loc2 < CAP);
        float gg1 = k1 ? p1 : 0.f, gg2 = k2 ? p2 : 0.f;
        float den = gg1 + gg2;
        den = fmaxf(den, 1.1920929e-07f);
        g_w1[s] = gg1 / den;
        g_w2[s] = gg2 / den;
        int sl1 = k1 ? (e1 * CAP + loc1) : -1;
        int sl2 = k2 ? (e2 * CAP + loc2) : -1;
        g_slot1[s] = sl1; g_slot2[s] = sl2;
        if (sl1 >= 0) g_slot2tok[sl1] = s;
        if (sl2 >= 0) g_slot2tok[sl2] = s;
    }

    if (tid == 0 && out_size > S_TOK * MDIM) {
        float la = 0.f;
#pragma unroll
        for (int e = 0; e < NEXP; e++)
            la += (sh_me[e] / (float)S_TOK) * ((float)sh_ce[e] / (float)S_TOK);
        out[(size_t)S_TOK * MDIM] = la * (float)NEXP;
    }
}

// ---------------- fp16 tensor-core GEMM: 4-stage pipeline, fused indirect A gather ----------------
// CTA tile 128x128x16, 8 warps (warp tile 32x64), mma.m16n8k16.f16
#define BM 128
#define BN 128
#define BK 16
#define NSTG (MDIM / BK)            // 64
#define NPIPE 4
#define AH 24                       // halves per A smem row (16 + 8 pad; banks 12*grp+tg distinct)
#define BH 24                       // halves per B smem row ([n][k] layout)
#define ABUF_H (BM * AH)            // 3072 halves
#define BBUF_H (BN * BH)            // 3072 halves
#define BUFSZ_H (ABUF_H + BBUF_H)   // 6144 halves = 12288 B
#define GEMM_SMEM (NPIPE * BUFSZ_H * 2)   // 49152 bytes

__global__ void __launch_bounds__(256, 2) k_gemm_mma(const __half* __restrict__ Wt,
                                                     const float* __restrict__ bias) {
    extern __shared__ __half smh[];
    int tid = threadIdx.x, wid = tid >> 5, lane = tid & 31;
    int grp = lane >> 2, tg = lane & 3;
    int e = blockIdx.z;
    int row0 = blockIdx.y * BM;
    int col0 = blockIdx.x * BN;
    int wm = (wid & 3) * 32, wn = (wid >> 2) * 64;

    // loaders: each thread = 1 A chunk + 1 B chunk (16B) per stage
    int arow = tid >> 1, aq = tid & 1;     // A row 0..127, chunk 0..1
    int slotbase = e * CAP + row0;
    int t0 = g_slot2tok[slotbase + arow];
    const __half* asrc = g_xh + (size_t)(t0 < 0 ? 0 : t0) * MDIM + aq * 8;
    uint32_t asz = (t0 >= 0) ? 16u : 0u;
    const __half* bsrc = Wt + (size_t)e * MDIM * MDIM + (size_t)(col0 + arow) * MDIM + aq * 8;
    uint32_t s0 = smem_u32(smh);
    uint32_t a_dst_off = (uint32_t)(arow * AH + aq * 8) * 2u;
    uint32_t b_dst_off = (uint32_t)(ABUF_H + arow * BH + aq * 8) * 2u;

    // bias segments for this thread's output columns
    float2 bb[8];
#pragma unroll
    for (int nj = 0; nj < 8; nj++)
        bb[nj] = *(const float2*)(bias + (size_t)e * MDIM + col0 + wn + nj * 8 + tg * 2);

    float d[2][8][4];
#pragma unroll
    for (int mi = 0; mi < 2; mi++)
#pragma unroll
        for (int nj = 0; nj < 8; nj++)
#pragma unroll
            for (int q = 0; q < 4; q++) d[mi][nj][q] = 0.f;

#define LOAD_STAGE(buf, k0) do {                                               \
    uint32_t sb0 = s0 + (uint32_t)((buf) * BUFSZ_H) * 2u;                      \
    CP_ASYNC16Z(sb0 + a_dst_off, asrc + (k0), asz);                            \
    CP_ASYNC16(sb0 + b_dst_off, bsrc + (k0));                                  \
} while (0)

    // prologue: prefetch stages 0..2
#pragma unroll
    for (int p = 0; p < NPIPE - 1; p++) {
        LOAD_STAGE(p, p * BK);
        CP_COMMIT();
    }

    for (int s = 0; s < NSTG; s++) {
        int cur = s & (NPIPE - 1);
        if (s + NPIPE - 1 < NSTG)
            LOAD_STAGE((s + NPIPE - 1) & (NPIPE - 1), (s + NPIPE - 1) * BK);
        CP_COMMIT();
        CP_WAIT3();
        __syncthreads();

        const __half* As = smh + cur * BUFSZ_H;
        const __half* Bs = As + ABUF_H;

        uint32_t a[2][4];
#pragma unroll
        for (int mi = 0; mi < 2; mi++) {
            const __half* ap = As + (wm + mi * 16 + grp) * AH + 2 * tg;
            a[mi][0] = *(const uint32_t*)(ap);
            a[mi][1] = *(const uint32_t*)(ap + 8 * AH);
            a[mi][2] = *(const uint32_t*)(ap + 8);
            a[mi][3] = *(const uint32_t*)(ap + 8 * AH + 8);
        }
        uint32_t b[8][2];
#pragma unroll
        for (int nj = 0; nj < 8; nj++) {
            const __half* bp = Bs + (wn + nj * 8 + grp) * BH + 2 * tg;
            b[nj][0] = *(const uint32_t*)(bp);
            b[nj][1] = *(const uint32_t*)(bp + 8);
        }
#pragma unroll
        for (int mi = 0; mi < 2; mi++)
#pragma unroll
            for (int nj = 0; nj < 8; nj++)
                mma_f16(d[mi][nj], a[mi], b[nj]);
        __syncthreads();
    }

    // epilogue: write 32x64 warp tile + bias
    float* Cp = g_eout + (size_t)e * CAP * MDIM;
#pragma unroll
    for (int mi = 0; mi < 2; mi++) {
        int row = row0 + wm + mi * 16 + grp;
#pragma unroll
        for (int nj = 0; nj < 8; nj++) {
            int col = col0 + wn + nj * 8 + tg * 2;
            float2 v0, v1;
            v0.x = d[mi][nj][0] + bb[nj].x;
            v0.y = d[mi][nj][1] + bb[nj].y;
            v1.x = d[mi][nj][2] + bb[nj].x;
            v1.y = d[mi][nj][3] + bb[nj].y;
            *(float2*)(Cp + (size_t)row * MDIM + col) = v0;
            *(float2*)(Cp + (size_t)(row + 8) * MDIM + col) = v1;
        }
    }
}

// ---------------- combine ----------------
__global__ void k_combine(float* __restrict__ out) {
    int s = blockIdx.x;
    float w1 = g_w1[s], w2 = g_w2[s];
    int sl1 = g_slot1[s], sl2 = g_slot2[s];
    int i = threadIdx.x;
    float4 r = make_float4(0.f, 0.f, 0.f, 0.f);
    if (sl1 >= 0) {
        float4 v = ((const float4*)(g_eout + (size_t)sl1 * MDIM))[i];
        r.x += w1 * v.x; r.y += w1 * v.y; r.z += w1 * v.z; r.w += w1 * v.w;
    }
    if (sl2 >= 0) {
        float4 v = ((const float4*)(g_eout + (size_t)sl2 * MDIM))[i];
        r.x += w2 * v.x; r.y += w2 * v.y; r.z += w2 * v.z; r.w += w2 * v.w;
    }
    ((float4*)(out + (size_t)s * MDIM))[i] = r;
}

// ---------------- launch ----------------
extern "C" void kernel_launch(void* const* d_in, const int* in_sizes, int n_in,
                              void* d_out, int out_size) {
    const float* x  = (const float*)d_in[0];   // [2,2048,1024]
    const float* wg = (const float*)d_in[1];   // [1024,8]
    const float* ew = (const float*)d_in[2];   // [8,1024,1024]
    const float* eb = (const float*)d_in[3];   // [8,1024]
    float* out = (float*)d_out;

    cudaFuncSetAttribute(k_gemm_mma, cudaFuncAttributeMaxDynamicSharedMemorySize, GEMM_SMEM);

    k_gate<<<GATE_BLOCKS, 256>>>(x, wg);
    dim3 wt(MDIM / 32, MDIM / 32, NEXP);
    k_wh<<<wt, dim3(32, 8, 1)>>>(ew);
    k_scan<<<1, SCAN_T>>>(out, out_size);
    dim3 gg(MDIM / BN, CAP / BM, NEXP);   // 8 x 8 x 8
    __half* wh_ptr;
    cudaGetSymbolAddress((void**)&wh_ptr, g_wh);
    k_gemm_mma<<<gg, 256, GEMM_SMEM>>>(wh_ptr, eb);
    k_combine<<<S_TOK, 256>>>(out);
}

// round 13
// speedup vs baseline: 1.1912x; 1.0366x over previous
#include <cuda_runtime.h>
#include <cuda_fp16.h>
#include <math.h>
#include <stdint.h>

#define S_TOK 4096
#define MDIM  1024
#define NEXP  8
#define CAP   1024
#define NSLOT (NEXP*CAP)        // 8192
#define GATE_BLOCKS (S_TOK/8)   // 512

// ---------------- device scratch (no allocations allowed) ----------------
__device__ int    g_e1[S_TOK], g_e2[S_TOK];
__device__ float  g_p1[S_TOK], g_p2[S_TOK];
__device__ float  g_w1[S_TOK], g_w2[S_TOK];
__device__ int    g_slot1[S_TOK], g_slot2[S_TOK];
__device__ int    g_slot2tok[NSLOT];
__device__ float  g_me_part[GATE_BLOCKS*NEXP];
__device__ int    g_ce_part[GATE_BLOCKS*NEXP];
__device__ float  g_eout[(size_t)NSLOT*MDIM];       // 32 MB (expert outputs)
__device__ __half g_xh[(size_t)S_TOK*MDIM];         // 8 MB  (x in fp16)
__device__ __half g_wh[(size_t)NEXP*MDIM*MDIM];     // 16 MB (W transposed [e][n][k] fp16)

// ---------------- helpers ----------------
__device__ __forceinline__ uint32_t smem_u32(const void* p) {
    uint32_t a;
    asm("{ .reg .u64 t; cvta.to.shared.u64 t, %1; cvt.u32.u64 %0, t; }" : "=r"(a) : "l"(p));
    return a;
}
__device__ __forceinline__ void mma_f16(float* d, const uint32_t* a, const uint32_t* b) {
    asm volatile(
        "mma.sync.aligned.m16n8k16.row.col.f32.f16.f16.f32 "
        "{%0,%1,%2,%3}, {%4,%5,%6,%7}, {%8,%9}, {%0,%1,%2,%3};"
        : "+f"(d[0]), "+f"(d[1]), "+f"(d[2]), "+f"(d[3])
        : "r"(a[0]), "r"(a[1]), "r"(a[2]), "r"(a[3]), "r"(b[0]), "r"(b[1]));
}
#define CP_ASYNC16(dst, src) \
    asm volatile("cp.async.cg.shared.global [%0], [%1], 16;" :: "r"(dst), "l"(src))
#define CP_ASYNC16Z(dst, src, sz) \
    asm volatile("cp.async.cg.shared.global [%0], [%1], 16, %2;" :: "r"(dst), "l"(src), "r"(sz))
#define CP_COMMIT() asm volatile("cp.async.commit_group;" ::: "memory")
#define CP_WAIT2()  asm volatile("cp.async.wait_group 2;" ::: "memory")

// ---------------- gating (+ fused slot-map init + fused x->fp16 convert) ----------------
__global__ void k_gate(const float* __restrict__ x, const float* __restrict__ wg) {
    if (threadIdx.x < 16) g_slot2tok[blockIdx.x * 16 + threadIdx.x] = -1;

    int warp = threadIdx.x >> 5, lane = threadIdx.x & 31;
    int s = blockIdx.x * 8 + warp;

    float acc[NEXP];
#pragma unroll
    for (int e = 0; e < NEXP; e++) acc[e] = 0.f;

    const float* xr = x + (size_t)s * MDIM;
    __half* xh = g_xh + (size_t)s * MDIM;
    for (int m = lane; m < MDIM; m += 32) {
        float xv = xr[m];
        xh[m] = __float2half_rn(xv);          // fused fp16 conversion
        const float4* w4 = (const float4*)(wg + (size_t)m * NEXP);
        float4 w0 = w4[0], w1 = w4[1];
        acc[0] += xv * w0.x; acc[1] += xv * w0.y;
        acc[2] += xv * w0.z; acc[3] += xv * w0.w;
        acc[4] += xv * w1.x; acc[5] += xv * w1.y;
        acc[6] += xv * w1.z; acc[7] += xv * w1.w;
    }
#pragma unroll
    for (int o = 16; o > 0; o >>= 1) {
#pragma unroll
        for (int e = 0; e < NEXP; e++)
            acc[e] += __shfl_down_sync(0xFFFFFFFFu, acc[e], o);
    }

    __shared__ float sh_g[8][NEXP];
    __shared__ int   sh_e1[8];

    if (lane == 0) {
        float mx = acc[0];
#pragma unroll
        for (int e = 1; e < NEXP; e++) mx = fmaxf(mx, acc[e]);
        float ex[NEXP]; float sum = 0.f;
#pragma unroll
        for (int e = 0; e < NEXP; e++) { ex[e] = expf(acc[e] - mx); sum += ex[e]; }
        float inv = 1.f / sum;

        int e1 = 0; float b1 = acc[0];
#pragma unroll
        for (int e = 1; e < NEXP; e++) if (acc[e] > b1) { b1 = acc[e]; e1 = e; }
        int e2 = -1; float b2 = -3.4e38f;
#pragma unroll
        for (int e = 0; e < NEXP; e++) if (e != e1 && acc[e] > b2) { b2 = acc[e]; e2 = e; }

        float p1 = 0.f, p2 = 0.f;
#pragma unroll
        for (int e = 0; e < NEXP; e++) {
            float ge = ex[e] * inv;
            if (e == e1) p1 = ge;
            if (e == e2) p2 = ge;
            sh_g[warp][e] = ge;
        }
        g_e1[s] = e1; g_e2[s] = e2;
        g_p1[s] = p1; g_p2[s] = p2;
        sh_e1[warp] = e1;
    }
    __syncthreads();

    if (threadIdx.x < NEXP) {
        int e = threadIdx.x;
        float ms = 0.f; int cs = 0;
#pragma unroll
        for (int w = 0; w < 8; w++) { ms += sh_g[w][e]; cs += (sh_e1[w] == e); }
        g_me_part[blockIdx.x * NEXP + e] = ms;
        g_ce_part[blockIdx.x * NEXP + e] = cs;
    }
}

// ---------------- W transpose + fp16 convert: [e][k][n] -> [e][n][k] ----------------
__global__ void k_wh(const float* __restrict__ W) {
    __shared__ float t[32][33];
    int e = blockIdx.z;
    int n0 = blockIdx.x * 32, k0 = blockIdx.y * 32;
    const float* src = W + (size_t)e * MDIM * MDIM;
    __half* dst = g_wh + (size_t)e * MDIM * MDIM;
    int tx = threadIdx.x, ty = threadIdx.y;   // 32 x 8
#pragma unroll
    for (int i = 0; i < 32; i += 8)
        t[ty + i][tx] = src[(size_t)(k0 + ty + i) * MDIM + n0 + tx];
    __syncthreads();
#pragma unroll
    for (int i = 0; i < 32; i += 8)
        dst[(size_t)(n0 + ty + i) * MDIM + k0 + tx] = __float2half_rn(t[tx][ty + i]);
}

// ---------------- scan (512 threads) ----------------
#define SCAN_T 512
__global__ void k_scan(float* __restrict__ out, int out_size) {
    const int T = SCAN_T, PT = S_TOK / T;
    int tid = threadIdx.x;

    __shared__ int   sc1[T][NEXP], sc2[T][NEXP];
    __shared__ float sh_me[NEXP];
    __shared__ int   sh_ce[NEXP];
    __shared__ int   tot1[NEXP];

    if (tid < NEXP) {
        float ms = 0.f; int cs = 0;
        for (int b = 0; b < GATE_BLOCKS; b++) {
            ms += g_me_part[b * NEXP + tid];
            cs += g_ce_part[b * NEXP + tid];
        }
        sh_me[tid] = ms; sh_ce[tid] = cs;
    }

    int c1[NEXP], c2[NEXP];
#pragma unroll
    for (int e = 0; e < NEXP; e++) { c1[e] = 0; c2[e] = 0; }
    for (int i = 0; i < PT; i++) {
        int s = tid * PT + i;
        c1[g_e1[s]]++;
        c2[g_e2[s]]++;
    }
#pragma unroll
    for (int e = 0; e < NEXP; e++) { sc1[tid][e] = c1[e]; sc2[tid][e] = c2[e]; }
    __syncthreads();

    for (int off = 1; off < T; off *= 2) {
        int v1[NEXP], v2[NEXP];
        if (tid >= off) {
#pragma unroll
            for (int e = 0; e < NEXP; e++) { v1[e] = sc1[tid - off][e]; v2[e] = sc2[tid - off][e]; }
        }
        __syncthreads();
        if (tid >= off) {
#pragma unroll
            for (int e = 0; e < NEXP; e++) { sc1[tid][e] += v1[e]; sc2[tid][e] += v2[e]; }
        }
        __syncthreads();
    }
    if (tid < NEXP) tot1[tid] = sc1[T - 1][tid];

    int b1[NEXP], b2[NEXP];
#pragma unroll
    for (int e = 0; e < NEXP; e++) { b1[e] = sc1[tid][e] - c1[e]; b2[e] = sc2[tid][e] - c2[e]; }
    __syncthreads();

    for (int i = 0; i < PT; i++) {
        int s = tid * PT + i;
        int e1 = g_e1[s], e2 = g_e2[s];
        int loc1 = b1[e1]++;
        int loc2 = b2[e2]++ + tot1[e2];
        float p1 = g_p1[s], p2 = g_p2[s];
        bool k1 = (loc1 < CAP), k2 = (loc2 < CAP);
        float gg1 = k1 ? p1 : 0.f, gg2 = k2 ? p2 : 0.f;
        float den = gg1 + gg2;
        den = fmaxf(den, 1.1920929e-07f);
        g_w1[s] = gg1 / den;
        g_w2[s] = gg2 / den;
        int sl1 = k1 ? (e1 * CAP + loc1) : -1;
        int sl2 = k2 ? (e2 * CAP + loc2) : -1;
        g_slot1[s] = sl1; g_slot2[s] = sl2;
        if (sl1 >= 0) g_slot2tok[sl1] = s;
        if (sl2 >= 0) g_slot2tok[sl2] = s;
    }

    if (tid == 0 && out_size > S_TOK * MDIM) {
        float la = 0.f;
#pragma unroll
        for (int e = 0; e < NEXP; e++)
            la += (sh_me[e] / (float)S_TOK) * ((float)sh_ce[e] / (float)S_TOK);
        out[(size_t)S_TOK * MDIM] = la * (float)NEXP;
    }
}

// ---------------- fp16 tensor-core GEMM: BK=32, 3-stage pipeline, fused indirect A gather ----------------
// CTA tile 128x128x32, 8 warps (warp tile 32x64), mma.m16n8k16.f16
#define BM 128
#define BN 128
#define BK 32
#define NSTG (MDIM / BK)            // 32
#define NPIPE 3
#define AH 40                       // halves per A smem row (32 + 8 pad; words row*20+tg all-distinct)
#define BH 40                       // halves per B smem row ([n][k] layout)
#define ABUF_H (BM * AH)            // 5120 halves
#define BBUF_H (BN * BH)            // 5120 halves
#define BUFSZ_H (ABUF_H + BBUF_H)   // 10240 halves = 20480 B
#define GEMM_SMEM (NPIPE * BUFSZ_H * 2)   // 61440 bytes

__global__ void __launch_bounds__(256, 2) k_gemm_mma(const __half* __restrict__ Wt,
                                                     const float* __restrict__ bias) {
    extern __shared__ __half smh[];
    int tid = threadIdx.x, wid = tid >> 5, lane = tid & 31;
    int grp = lane >> 2, tg = lane & 3;
    int e = blockIdx.z;
    int row0 = blockIdx.y * BM;
    int col0 = blockIdx.x * BN;
    int wm = (wid & 3) * 32, wn = (wid >> 2) * 64;

    // loaders: each thread = 2 A chunks + 2 B chunks (16B each) per stage
    int arow = tid >> 1, aq = tid & 1;     // row 0..127, 32B half-row aq
    int slotbase = e * CAP + row0;
    int t0 = g_slot2tok[slotbase + arow];
    const __half* asrc = g_xh + (size_t)(t0 < 0 ? 0 : t0) * MDIM + aq * 16;
    uint32_t asz = (t0 >= 0) ? 16u : 0u;
    const __half* bsrc = Wt + (size_t)e * MDIM * MDIM + (size_t)(col0 + arow) * MDIM + aq * 16;
    uint32_t s0 = smem_u32(smh);
    uint32_t a_dst_off = (uint32_t)(arow * AH + aq * 16) * 2u;
    uint32_t b_dst_off = (uint32_t)(ABUF_H + arow * BH + aq * 16) * 2u;

    // bias segments for this thread's output columns
    float2 bb[8];
#pragma unroll
    for (int nj = 0; nj < 8; nj++)
        bb[nj] = *(const float2*)(bias + (size_t)e * MDIM + col0 + wn + nj * 8 + tg * 2);

    float d[2][8][4];
#pragma unroll
    for (int mi = 0; mi < 2; mi++)
#pragma unroll
        for (int nj = 0; nj < 8; nj++)
#pragma unroll
            for (int q = 0; q < 4; q++) d[mi][nj][q] = 0.f;

#define LOAD_STAGE(buf, k0) do {                                               \
    uint32_t sb0 = s0 + (uint32_t)((buf) * BUFSZ_H) * 2u;                      \
    CP_ASYNC16Z(sb0 + a_dst_off,       asrc + (k0),     asz);                  \
    CP_ASYNC16Z(sb0 + a_dst_off + 16u, asrc + (k0) + 8, asz);                  \
    CP_ASYNC16(sb0 + b_dst_off,        bsrc + (k0));                           \
    CP_ASYNC16(sb0 + b_dst_off + 16u,  bsrc + (k0) + 8);                       \
} while (0)

    // prologue: prefetch stages 0..1
#pragma unroll
    for (int p = 0; p < NPIPE - 1; p++) {
        LOAD_STAGE(p, p * BK);
        CP_COMMIT();
    }

    for (int s = 0; s < NSTG; s++) {
        int cur = s % NPIPE;
        if (s + NPIPE - 1 < NSTG)
            LOAD_STAGE((s + NPIPE - 1) % NPIPE, (s + NPIPE - 1) * BK);
        CP_COMMIT();
        CP_WAIT2();
        __syncthreads();

        const __half* As = smh + cur * BUFSZ_H;
        const __half* Bs = As + ABUF_H;

#pragma unroll
        for (int ks = 0; ks < 2; ks++) {
            int kb = ks * 16;
            uint32_t a[2][4];
#pragma unroll
            for (int mi = 0; mi < 2; mi++) {
                const __half* ap = As + (wm + mi * 16 + grp) * AH + kb + 2 * tg;
                a[mi][0] = *(const uint32_t*)(ap);
                a[mi][1] = *(const uint32_t*)(ap + 8 * AH);
                a[mi][2] = *(const uint32_t*)(ap + 8);
                a[mi][3] = *(const uint32_t*)(ap + 8 * AH + 8);
            }
            uint32_t b[8][2];
#pragma unroll
            for (int nj = 0; nj < 8; nj++) {
                const __half* bp = Bs + (wn + nj * 8 + grp) * BH + kb + 2 * tg;
                b[nj][0] = *(const uint32_t*)(bp);
                b[nj][1] = *(const uint32_t*)(bp + 8);
            }
#pragma unroll
            for (int mi = 0; mi < 2; mi++)
#pragma unroll
                for (int nj = 0; nj < 8; nj++)
                    mma_f16(d[mi][nj], a[mi], b[nj]);
        }
        __syncthreads();
    }

    // epilogue: write 32x64 warp tile + bias
    float* Cp = g_eout + (size_t)e * CAP * MDIM;
#pragma unroll
    for (int mi = 0; mi < 2; mi++) {
        int row = row0 + wm + mi * 16 + grp;
#pragma unroll
        for (int nj = 0; nj < 8; nj++) {
            int col = col0 + wn + nj * 8 + tg * 2;
            float2 v0, v1;
            v0.x = d[mi][nj][0] + bb[nj].x;
            v0.y = d[mi][nj][1] + bb[nj].y;
            v1.x = d[mi][nj][2] + bb[nj].x;
            v1.y = d[mi][nj][3] + bb[nj].y;
            *(float2*)(Cp + (size_t)row * MDIM + col) = v0;
            *(float2*)(Cp + (size_t)(row + 8) * MDIM + col) = v1;
        }
    }
}

// ---------------- combine ----------------
__global__ void k_combine(float* __restrict__ out) {
    int s = blockIdx.x;
    float w1 = g_w1[s], w2 = g_w2[s];
    int sl1 = g_slot1[s], sl2 = g_slot2[s];
    int i = threadIdx.x;
    float4 r = make_float4(0.f, 0.f, 0.f, 0.f);
    if (sl1 >= 0) {
        float4 v = ((const float4*)(g_eout + (size_t)sl1 * MDIM))[i];
        r.x += w1 * v.x; r.y += w1 * v.y; r.z += w1 * v.z; r.w += w1 * v.w;
    }
    if (sl2 >= 0) {
        float4 v = ((const float4*)(g_eout + (size_t)sl2 * MDIM))[i];
        r.x += w2 * v.x; r.y += w2 * v.y; r.z += w2 * v.z; r.w += w2 * v.w;
    }
    ((float4*)(out + (size_t)s * MDIM))[i] = r;
}

// ---------------- launch ----------------
extern "C" void kernel_launch(void* const* d_in, const int* in_sizes, int n_in,
                              void* d_out, int out_size) {
    const float* x  = (const float*)d_in[0];   // [2,2048,1024]
    const float* wg = (const float*)d_in[1];   // [1024,8]
    const float* ew = (const float*)d_in[2];   // [8,1024,1024]
    const float* eb = (const float*)d_in[3];   // [8,1024]
    float* out = (float*)d_out;

    cudaFuncSetAttribute(k_gemm_mma, cudaFuncAttributeMaxDynamicSharedMemorySize, GEMM_SMEM);

    k_gate<<<GATE_BLOCKS, 256>>>(x, wg);
    dim3 wt(MDIM / 32, MDIM / 32, NEXP);
    k_wh<<<wt, dim3(32, 8, 1)>>>(ew);
    k_scan<<<1, SCAN_T>>>(out, out_size);
    dim3 gg(MDIM / BN, CAP / BM, NEXP);   // 8 x 8 x 8
    __half* wh_ptr;
    cudaGetSymbolAddress((void**)&wh_ptr, g_wh);
    k_gemm_mma<<<gg, 256, GEMM_SMEM>>>(wh_ptr, eb);
    k_combine<<<S_TOK, 256>>>(out);
}

// round 15
// speedup vs baseline: 1.3174x; 1.1059x over previous
#include <cuda_runtime.h>
#include <cuda_fp16.h>
#include <math.h>
#include <stdint.h>

#define S_TOK 4096
#define MDIM  1024
#define NEXP  8
#define CAP   1024
#define NSLOT (NEXP*CAP)        // 8192
#define GATE_BLOCKS (S_TOK/8)   // 512

// ---------------- device scratch (no allocations allowed) ----------------
__device__ int    g_e1[S_TOK], g_e2[S_TOK];
__device__ float  g_p1[S_TOK], g_p2[S_TOK];
__device__ float  g_w1[S_TOK], g_w2[S_TOK];
__device__ int    g_slot1[S_TOK], g_slot2[S_TOK];
__device__ int    g_slot2tok[NSLOT];
__device__ float  g_me_part[GATE_BLOCKS*NEXP];
__device__ int    g_ce_part[GATE_BLOCKS*NEXP];
__device__ float  g_eout[(size_t)NSLOT*MDIM];       // 32 MB (expert outputs)
__device__ __half g_xh[(size_t)S_TOK*MDIM];         // 8 MB  (x in fp16)
__device__ __half g_wh[(size_t)NEXP*MDIM*MDIM];     // 16 MB (W transposed [e][n][k] fp16)

// ---------------- helpers ----------------
__device__ __forceinline__ uint32_t smem_u32(const void* p) {
    uint32_t a;
    asm("{ .reg .u64 t; cvta.to.shared.u64 t, %1; cvt.u32.u64 %0, t; }" : "=r"(a) : "l"(p));
    return a;
}
__device__ __forceinline__ void mma_f16(float* d, const uint32_t* a, const uint32_t* b) {
    asm volatile(
        "mma.sync.aligned.m16n8k16.row.col.f32.f16.f16.f32 "
        "{%0,%1,%2,%3}, {%4,%5,%6,%7}, {%8,%9}, {%0,%1,%2,%3};"
        : "+f"(d[0]), "+f"(d[1]), "+f"(d[2]), "+f"(d[3])
        : "r"(a[0]), "r"(a[1]), "r"(a[2]), "r"(a[3]), "r"(b[0]), "r"(b[1]));
}
__device__ __forceinline__ void ldmx4(uint32_t& r0, uint32_t& r1, uint32_t& r2, uint32_t& r3,
                                      uint32_t addr) {
    asm volatile("ldmatrix.sync.aligned.m8n8.x4.shared.b16 {%0,%1,%2,%3}, [%4];"
        : "=r"(r0), "=r"(r1), "=r"(r2), "=r"(r3) : "r"(addr));
}
#define CP_ASYNC16(dst, src) \
    asm volatile("cp.async.cg.shared.global [%0], [%1], 16;" :: "r"(dst), "l"(src))
#define CP_ASYNC16Z(dst, src, sz) \
    asm volatile("cp.async.cg.shared.global [%0], [%1], 16, %2;" :: "r"(dst), "l"(src), "r"(sz))
#define CP_COMMIT() asm volatile("cp.async.commit_group;" ::: "memory")
#define CP_WAIT1()  asm volatile("cp.async.wait_group 1;" ::: "memory")

// ---------------- gating (+ fused slot-map init + fused x->fp16 convert) ----------------
__global__ void k_gate(const float* __restrict__ x, const float* __restrict__ wg) {
    if (threadIdx.x < 16) g_slot2tok[blockIdx.x * 16 + threadIdx.x] = -1;

    int warp = threadIdx.x >> 5, lane = threadIdx.x & 31;
    int s = blockIdx.x * 8 + warp;

    float acc[NEXP];
#pragma unroll
    for (int e = 0; e < NEXP; e++) acc[e] = 0.f;

    const float* xr = x + (size_t)s * MDIM;
    __half* xh = g_xh + (size_t)s * MDIM;
    for (int m = lane; m < MDIM; m += 32) {
        float xv = xr[m];
        xh[m] = __float2half_rn(xv);          // fused fp16 conversion
        const float4* w4 = (const float4*)(wg + (size_t)m * NEXP);
        float4 w0 = w4[0], w1 = w4[1];
        acc[0] += xv * w0.x; acc[1] += xv * w0.y;
        acc[2] += xv * w0.z; acc[3] += xv * w0.w;
        acc[4] += xv * w1.x; acc[5] += xv * w1.y;
        acc[6] += xv * w1.z; acc[7] += xv * w1.w;
    }
#pragma unroll
    for (int o = 16; o > 0; o >>= 1) {
#pragma unroll
        for (int e = 0; e < NEXP; e++)
            acc[e] += __shfl_down_sync(0xFFFFFFFFu, acc[e], o);
    }

    __shared__ float sh_g[8][NEXP];
    __shared__ int   sh_e1[8];

    if (lane == 0) {
        float mx = acc[0];
#pragma unroll
        for (int e = 1; e < NEXP; e++) mx = fmaxf(mx, acc[e]);
        float ex[NEXP]; float sum = 0.f;
#pragma unroll
        for (int e = 0; e < NEXP; e++) { ex[e] = expf(acc[e] - mx); sum += ex[e]; }
        float inv = 1.f / sum;

        int e1 = 0; float b1 = acc[0];
#pragma unroll
        for (int e = 1; e < NEXP; e++) if (acc[e] > b1) { b1 = acc[e]; e1 = e; }
        int e2 = -1; float b2 = -3.4e38f;
#pragma unroll
        for (int e = 0; e < NEXP; e++) if (e != e1 && acc[e] > b2) { b2 = acc[e]; e2 = e; }

        float p1 = 0.f, p2 = 0.f;
#pragma unroll
        for (int e = 0; e < NEXP; e++) {
            float ge = ex[e] * inv;
            if (e == e1) p1 = ge;
            if (e == e2) p2 = ge;
            sh_g[warp][e] = ge;
        }
        g_e1[s] = e1; g_e2[s] = e2;
        g_p1[s] = p1; g_p2[s] = p2;
        sh_e1[warp] = e1;
    }
    __syncthreads();

    if (threadIdx.x < NEXP) {
        int e = threadIdx.x;
        float ms = 0.f; int cs = 0;
#pragma unroll
        for (int w = 0; w < 8; w++) { ms += sh_g[w][e]; cs += (sh_e1[w] == e); }
        g_me_part[blockIdx.x * NEXP + e] = ms;
        g_ce_part[blockIdx.x * NEXP + e] = cs;
    }
}

// ---------------- W transpose + fp16 convert: [e][k][n] -> [e][n][k] ----------------
__global__ void k_wh(const float* __restrict__ W) {
    __shared__ float t[32][33];
    int e = blockIdx.z;
    int n0 = blockIdx.x * 32, k0 = blockIdx.y * 32;
    const float* src = W + (size_t)e * MDIM * MDIM;
    __half* dst = g_wh + (size_t)e * MDIM * MDIM;
    int tx = threadIdx.x, ty = threadIdx.y;   // 32 x 8
#pragma unroll
    for (int i = 0; i < 32; i += 8)
        t[ty + i][tx] = src[(size_t)(k0 + ty + i) * MDIM + n0 + tx];
    __syncthreads();
#pragma unroll
    for (int i = 0; i < 32; i += 8)
        dst[(size_t)(n0 + ty + i) * MDIM + k0 + tx] = __float2half_rn(t[tx][ty + i]);
}

// ---------------- scan (512 threads) ----------------
#define SCAN_T 512
__global__ void k_scan(float* __restrict__ out, int out_size) {
    const int T = SCAN_T, PT = S_TOK / T;
    int tid = threadIdx.x;

    __shared__ int   sc1[T][NEXP], sc2[T][NEXP];
    __shared__ float sh_me[NEXP];
    __shared__ int   sh_ce[NEXP];
    __shared__ int   tot1[NEXP];

    if (tid < NEXP) {
        float ms = 0.f; int cs = 0;
        for (int b = 0; b < GATE_BLOCKS; b++) {
            ms += g_me_part[b * NEXP + tid];
            cs += g_ce_part[b * NEXP + tid];
        }
        sh_me[tid] = ms; sh_ce[tid] = cs;
    }

    int c1[NEXP], c2[NEXP];
#pragma unroll
    for (int e = 0; e < NEXP; e++) { c1[e] = 0; c2[e] = 0; }
    for (int i = 0; i < PT; i++) {
        int s = tid * PT + i;
        c1[g_e1[s]]++;
        c2[g_e2[s]]++;
    }
#pragma unroll
    for (int e = 0; e < NEXP; e++) { sc1[tid][e] = c1[e]; sc2[tid][e] = c2[e]; }
    __syncthreads();

    for (int off = 1; off < T; off *= 2) {
        int v1[NEXP], v2[NEXP];
        if (tid >= off) {
#pragma unroll
            for (int e = 0; e < NEXP; e++) { v1[e] = sc1[tid - off][e]; v2[e] = sc2[tid - off][e]; }
        }
        __syncthreads();
        if (tid >= off) {
#pragma unroll
            for (int e = 0; e < NEXP; e++) { sc1[tid][e] += v1[e]; sc2[tid][e] += v2[e]; }
        }
        __syncthreads();
    }
    if (tid < NEXP) tot1[tid] = sc1[T - 1][tid];

    int b1[NEXP], b2[NEXP];
#pragma unroll
    for (int e = 0; e < NEXP; e++) { b1[e] = sc1[tid][e] - c1[e]; b2[e] = sc2[tid][e] - c2[e]; }
    __syncthreads();

    for (int i = 0; i < PT; i++) {
        int s = tid * PT + i;
        int e1 = g_e1[s], e2 = g_e2[s];
        int loc1 = b1[e1]++;
        int loc2 = b2[e2]++ + tot1[e2];
        float p1 = g_p1[s], p2 = g_p2[s];
        bool k1 = (loc1 < CAP), k2 = (loc2 < CAP);
        float gg1 = k1 ? p1 : 0.f, gg2 = k2 ? p2 : 0.f;
        float den = gg1 + gg2;
        den = fmaxf(den, 1.1920929e-07f);
        g_w1[s] = gg1 / den;
        g_w2[s] = gg2 / den;
        int sl1 = k1 ? (e1 * CAP + loc1) : -1;
        int sl2 = k2 ? (e2 * CAP + loc2) : -1;
        g_slot1[s] = sl1; g_slot2[s] = sl2;
        if (sl1 >= 0) g_slot2tok[sl1] = s;
        if (sl2 >= 0) g_slot2tok[sl2] = s;
    }

    if (tid == 0 && out_size > S_TOK * MDIM) {
        float la = 0.f;
#pragma unroll
        for (int e = 0; e < NEXP; e++)
            la += (sh_me[e] / (float)S_TOK) * ((float)sh_ce[e] / (float)S_TOK);
        out[(size_t)S_TOK * MDIM] = la * (float)NEXP;
    }
}

// ---------------- fp16 tensor-core GEMM: BK=32, 3-stage, ldmatrix frags, single sync ----------------
// CTA tile 128x128x32, 8 warps (warp tile 32x64), mma.m16n8k16.f16
#define BM 128
#define BN 128
#define BK 32
#define NSTG (MDIM / BK)            // 32
#define NPIPE 3
#define AH 40                       // halves per A smem row (32 + 8 pad; conflict-free for ldmatrix)
#define BH 40                       // halves per B smem row ([n][k] layout)
#define ABUF_H (BM * AH)            // 5120 halves
#define BBUF_H (BN * BH)            // 5120 halves
#define BUFSZ_H (ABUF_H + BBUF_H)   // 10240 halves = 20480 B
#define GEMM_SMEM (NPIPE * BUFSZ_H * 2)   // 61440 bytes

__global__ void __launch_bounds__(256, 2) k_gemm_mma(const __half* __restrict__ Wt,
                                                     const float* __restrict__ bias) {
    extern __shared__ __half smh[];
    int tid = threadIdx.x, wid = tid >> 5, lane = tid & 31;
    int grp = lane >> 2, tg = lane & 3;
    int e = blockIdx.z;
    int row0 = blockIdx.y * BM;
    int col0 = blockIdx.x * BN;
    int wm = (wid & 3) * 32, wn = (wid >> 2) * 64;

    // loaders: each thread = 2 A chunks + 2 B chunks (16B each) per stage
    int arow = tid >> 1, aq = tid & 1;     // row 0..127, 32B half-row aq
    int slotbase = e * CAP + row0;
    int t0 = g_slot2tok[slotbase + arow];
    const __half* asrc = g_xh + (size_t)(t0 < 0 ? 0 : t0) * MDIM + aq * 16;
    uint32_t asz = (t0 >= 0) ? 16u : 0u;
    const __half* bsrc = Wt + (size_t)e * MDIM * MDIM + (size_t)(col0 + arow) * MDIM + aq * 16;
    uint32_t s0 = smem_u32(smh);
    uint32_t a_dst_off = (uint32_t)(arow * AH + aq * 16) * 2u;
    uint32_t b_dst_off = (uint32_t)(ABUF_H + arow * BH + aq * 16) * 2u;

    // ldmatrix per-lane source offsets (bytes, relative to stage base, kb excluded)
    // A (x4): lanes 0-7 rows 0-7 k0 | 8-15 rows 8-15 k0 | 16-23 rows 0-7 k8 | 24-31 rows 8-15 k8
    uint32_t a_lm[2];
#pragma unroll
    for (int mi = 0; mi < 2; mi++)
        a_lm[mi] = (uint32_t)(((wm + mi * 16 + (lane & 15)) * AH + ((lane >> 4) * 8)) * 2);
    // B (x4) for nj pair p: lanes 0-7 n(2p)+0-7 k0 | 8-15 same n k8 | 16-23 n(2p+1) k0 | 24-31 n(2p+1) k8
    uint32_t b_lm[4];
#pragma unroll
    for (int p = 0; p < 4; p++)
        b_lm[p] = (uint32_t)((ABUF_H + (wn + (2 * p + (lane >> 4)) * 8 + (lane & 7)) * BH
                              + (((lane >> 3) & 1) * 8)) * 2);

    // bias segments for this thread's output columns
    float2 bb[8];
#pragma unroll
    for (int nj = 0; nj < 8; nj++)
        bb[nj] = *(const float2*)(bias + (size_t)e * MDIM + col0 + wn + nj * 8 + tg * 2);

    float d[2][8][4];
#pragma unroll
    for (int mi = 0; mi < 2; mi++)
#pragma unroll
        for (int nj = 0; nj < 8; nj++)
#pragma unroll
            for (int q = 0; q < 4; q++) d[mi][nj][q] = 0.f;

#define LOAD_STAGE(buf, k0) do {                                               \
    uint32_t sb0 = s0 + (uint32_t)((buf) * BUFSZ_H) * 2u;                      \
    CP_ASYNC16Z(sb0 + a_dst_off,       asrc + (k0),     asz);                  \
    CP_ASYNC16Z(sb0 + a_dst_off + 16u, asrc + (k0) + 8, asz);                  \
    CP_ASYNC16(sb0 + b_dst_off,        bsrc + (k0));                           \
    CP_ASYNC16(sb0 + b_dst_off + 16u,  bsrc + (k0) + 8);                       \
} while (0)

    // prologue: prefetch stages 0..1 (2 groups in flight)
#pragma unroll
    for (int p = 0; p < NPIPE - 1; p++) {
        LOAD_STAGE(p, p * BK);
        CP_COMMIT();
    }

    for (int s = 0; s < NSTG; s++) {
        int cur = s % NPIPE;
        CP_WAIT1();                 // group for stage s retired (≤1 pending)
        __syncthreads();            // data visible + prior compute done before overwrite below

        uint32_t base = s0 + (uint32_t)(cur * BUFSZ_H) * 2u;
#pragma unroll
        for (int ks = 0; ks < 2; ks++) {
            uint32_t kbyte = (uint32_t)(ks * 16 * 2);
            uint32_t a[2][4];
#pragma unroll
            for (int mi = 0; mi < 2; mi++)
                ldmx4(a[mi][0], a[mi][1], a[mi][2], a[mi][3], base + a_lm[mi] + kbyte);
            uint32_t b[8][2];
#pragma unroll
            for (int p = 0; p < 4; p++)
                ldmx4(b[2 * p][0], b[2 * p][1], b[2 * p + 1][0], b[2 * p + 1][1],
                      base + b_lm[p] + kbyte);
#pragma unroll
            for (int mi = 0; mi < 2; mi++)
#pragma unroll
                for (int nj = 0; nj < 8; nj++)
                    mma_f16(d[mi][nj], a[mi], b[nj]);
        }

        if (s + NPIPE - 1 < NSTG)
            LOAD_STAGE((s + NPIPE - 1) % NPIPE, (s + NPIPE - 1) * BK);
        CP_COMMIT();
    }

    // epilogue: write 32x64 warp tile + bias
    float* Cp = g_eout + (size_t)e * CAP * MDIM;
#pragma unroll
    for (int mi = 0; mi < 2; mi++) {
        int row = row0 + wm + mi * 16 + grp;
#pragma unroll
        for (int nj = 0; nj < 8; nj++) {
            int col = col0 + wn + nj * 8 + tg * 2;
            float2 v0, v1;
            v0.x = d[mi][nj][0] + bb[nj].x;
            v0.y = d[mi][nj][1] + bb[nj].y;
            v1.x = d[mi][nj][2] + bb[nj].x;
            v1.y = d[mi][nj][3] + bb[nj].y;
            *(float2*)(Cp + (size_t)row * MDIM + col) = v0;
            *(float2*)(Cp + (size_t)(row + 8) * MDIM + col) = v1;
        }
    }
}

// ---------------- combine ----------------
__global__ void k_combine(float* __restrict__ out) {
    int s = blockIdx.x;
    float w1 = g_w1[s], w2 = g_w2[s];
    int sl1 = g_slot1[s], sl2 = g_slot2[s];
    int i = threadIdx.x;
    float4 r = make_float4(0.f, 0.f, 0.f, 0.f);
    if (sl1 >= 0) {
        float4 v = ((const float4*)(g_eout + (size_t)sl1 * MDIM))[i];
        r.x += w1 * v.x; r.y += w1 * v.y; r.z += w1 * v.z; r.w += w1 * v.w;
    }
    if (sl2 >= 0) {
        float4 v = ((const float4*)(g_eout + (size_t)sl2 * MDIM))[i];
        r.x += w2 * v.x; r.y += w2 * v.y; r.z += w2 * v.z; r.w += w2 * v.w;
    }
    ((float4*)(out + (size_t)s * MDIM))[i] = r;
}

// ---------------- launch ----------------
extern "C" void kernel_launch(void* const* d_in, const int* in_sizes, int n_in,
                              void* d_out, int out_size) {
    const float* x  = (const float*)d_in[0];   // [2,2048,1024]
    const float* wg = (const float*)d_in[1];   // [1024,8]
    const float* ew = (const float*)d_in[2];   // [8,1024,1024]
    const float* eb = (const float*)d_in[3];   // [8,1024]
    float* out = (float*)d_out;

    cudaFuncSetAttribute(k_gemm_mma, cudaFuncAttributeMaxDynamicSharedMemorySize, GEMM_SMEM);

    k_gate<<<GATE_BLOCKS, 256>>>(x, wg);
    dim3 wt(MDIM / 32, MDIM / 32, NEXP);
    k_wh<<<wt, dim3(32, 8, 1)>>>(ew);
    k_scan<<<1, SCAN_T>>>(out, out_size);
    dim3 gg(MDIM / BN, CAP / BM, NEXP);   // 8 x 8 x 8
    __half* wh_ptr;
    cudaGetSymbolAddress((void**)&wh_ptr, g_wh);
    k_gemm_mma<<<gg, 256, GEMM_SMEM>>>(wh_ptr, eb);
    k_combine<<<S_TOK, 256>>>(out);
}

// round 16
// speedup vs baseline: 1.5248x; 1.1574x over previous
#include <cuda_runtime.h>
#include <cuda_fp16.h>
#include <math.h>
#include <stdint.h>

#define S_TOK 4096
#define MDIM  1024
#define NEXP  8
#define CAP   1024
#define NSLOT (NEXP*CAP)        // 8192
#define GATE_BLOCKS (S_TOK/8)   // 512

// ---------------- device scratch (no allocations allowed) ----------------
__device__ int    g_e1[S_TOK], g_e2[S_TOK];
__device__ float  g_p1[S_TOK], g_p2[S_TOK];
__device__ int    g_slot2tok[NSLOT];
__device__ float  g_wslot[NSLOT];
__device__ float  g_me_part[GATE_BLOCKS*NEXP];
__device__ int    g_ce_part[GATE_BLOCKS*NEXP];
__device__ __half g_xh[(size_t)S_TOK*MDIM];         // 8 MB  (x in fp16)
__device__ __half g_wh[(size_t)NEXP*MDIM*MDIM];     // 16 MB (W transposed [e][n][k] fp16)

// ---------------- helpers ----------------
__device__ __forceinline__ uint32_t smem_u32(const void* p) {
    uint32_t a;
    asm("{ .reg .u64 t; cvta.to.shared.u64 t, %1; cvt.u32.u64 %0, t; }" : "=r"(a) : "l"(p));
    return a;
}
__device__ __forceinline__ void mma_f16(float* d, const uint32_t* a, const uint32_t* b) {
    asm volatile(
        "mma.sync.aligned.m16n8k16.row.col.f32.f16.f16.f32 "
        "{%0,%1,%2,%3}, {%4,%5,%6,%7}, {%8,%9}, {%0,%1,%2,%3};"
        : "+f"(d[0]), "+f"(d[1]), "+f"(d[2]), "+f"(d[3])
        : "r"(a[0]), "r"(a[1]), "r"(a[2]), "r"(a[3]), "r"(b[0]), "r"(b[1]));
}
__device__ __forceinline__ void ldmx4(uint32_t& r0, uint32_t& r1, uint32_t& r2, uint32_t& r3,
                                      uint32_t addr) {
    asm volatile("ldmatrix.sync.aligned.m8n8.x4.shared.b16 {%0,%1,%2,%3}, [%4];"
        : "=r"(r0), "=r"(r1), "=r"(r2), "=r"(r3) : "r"(addr));
}
#define CP_ASYNC16(dst, src) \
    asm volatile("cp.async.cg.shared.global [%0], [%1], 16;" :: "r"(dst), "l"(src))
#define CP_ASYNC16Z(dst, src, sz) \
    asm volatile("cp.async.cg.shared.global [%0], [%1], 16, %2;" :: "r"(dst), "l"(src), "r"(sz))
#define CP_COMMIT() asm volatile("cp.async.commit_group;" ::: "memory")
#define CP_WAIT2()  asm volatile("cp.async.wait_group 2;" ::: "memory")

// ---------------- gating (+ slot-map init + x->fp16 convert + out zero) ----------------
__global__ void k_gate(const float* __restrict__ x, const float* __restrict__ wg,
                       float* __restrict__ out) {
    if (threadIdx.x < 16) g_slot2tok[blockIdx.x * 16 + threadIdx.x] = -1;
    // zero out[0 .. S_TOK*MDIM): 512 blocks x 2048 float4
    {
        float4* oz = (float4*)out + (size_t)blockIdx.x * 2048;
#pragma unroll
        for (int i = 0; i < 8; i++)
            oz[threadIdx.x + i * 256] = make_float4(0.f, 0.f, 0.f, 0.f);
    }

    int warp = threadIdx.x >> 5, lane = threadIdx.x & 31;
    int s = blockIdx.x * 8 + warp;

    float acc[NEXP];
#pragma unroll
    for (int e = 0; e < NEXP; e++) acc[e] = 0.f;

    const float* xr = x + (size_t)s * MDIM;
    __half* xh = g_xh + (size_t)s * MDIM;
    for (int m = lane; m < MDIM; m += 32) {
        float xv = xr[m];
        xh[m] = __float2half_rn(xv);
        const float4* w4 = (const float4*)(wg + (size_t)m * NEXP);
        float4 w0 = w4[0], w1 = w4[1];
        acc[0] += xv * w0.x; acc[1] += xv * w0.y;
        acc[2] += xv * w0.z; acc[3] += xv * w0.w;
        acc[4] += xv * w1.x; acc[5] += xv * w1.y;
        acc[6] += xv * w1.z; acc[7] += xv * w1.w;
    }
#pragma unroll
    for (int o = 16; o > 0; o >>= 1) {
#pragma unroll
        for (int e = 0; e < NEXP; e++)
            acc[e] += __shfl_down_sync(0xFFFFFFFFu, acc[e], o);
    }

    __shared__ float sh_g[8][NEXP];
    __shared__ int   sh_e1[8];

    if (lane == 0) {
        float mx = acc[0];
#pragma unroll
        for (int e = 1; e < NEXP; e++) mx = fmaxf(mx, acc[e]);
        float ex[NEXP]; float sum = 0.f;
#pragma unroll
        for (int e = 0; e < NEXP; e++) { ex[e] = expf(acc[e] - mx); sum += ex[e]; }
        float inv = 1.f / sum;

        int e1 = 0; float b1 = acc[0];
#pragma unroll
        for (int e = 1; e < NEXP; e++) if (acc[e] > b1) { b1 = acc[e]; e1 = e; }
        int e2 = -1; float b2 = -3.4e38f;
#pragma unroll
        for (int e = 0; e < NEXP; e++) if (e != e1 && acc[e] > b2) { b2 = acc[e]; e2 = e; }

        float p1 = 0.f, p2 = 0.f;
#pragma unroll
        for (int e = 0; e < NEXP; e++) {
            float ge = ex[e] * inv;
            if (e == e1) p1 = ge;
            if (e == e2) p2 = ge;
            sh_g[warp][e] = ge;
        }
        g_e1[s] = e1; g_e2[s] = e2;
        g_p1[s] = p1; g_p2[s] = p2;
        sh_e1[warp] = e1;
    }
    __syncthreads();

    if (threadIdx.x < NEXP) {
        int e = threadIdx.x;
        float ms = 0.f; int cs = 0;
#pragma unroll
        for (int w = 0; w < 8; w++) { ms += sh_g[w][e]; cs += (sh_e1[w] == e); }
        g_me_part[blockIdx.x * NEXP + e] = ms;
        g_ce_part[blockIdx.x * NEXP + e] = cs;
    }
}

// ---------------- W transpose + fp16 convert: [e][k][n] -> [e][n][k] ----------------
__global__ void k_wh(const float* __restrict__ W) {
    __shared__ float t[32][33];
    int e = blockIdx.z;
    int n0 = blockIdx.x * 32, k0 = blockIdx.y * 32;
    const float* src = W + (size_t)e * MDIM * MDIM;
    __half* dst = g_wh + (size_t)e * MDIM * MDIM;
    int tx = threadIdx.x, ty = threadIdx.y;   // 32 x 8
#pragma unroll
    for (int i = 0; i < 32; i += 8)
        t[ty + i][tx] = src[(size_t)(k0 + ty + i) * MDIM + n0 + tx];
    __syncthreads();
#pragma unroll
    for (int i = 0; i < 32; i += 8)
        dst[(size_t)(n0 + ty + i) * MDIM + k0 + tx] = __float2half_rn(t[tx][ty + i]);
}

// ---------------- scan (512 threads, parallel partial reduction) ----------------
#define SCAN_T 512
__global__ void k_scan(float* __restrict__ out, int out_size) {
    const int T = SCAN_T, PT = S_TOK / T;   // 8 tokens per thread
    int tid = threadIdx.x;
    int lane = tid & 31, warp = tid >> 5;   // 16 warps

    __shared__ int   sc1[T][NEXP], sc2[T][NEXP];
    __shared__ float wred_me[16][NEXP];
    __shared__ int   wred_ce[16][NEXP];
    __shared__ float sh_me[NEXP];
    __shared__ int   sh_ce[NEXP];
    __shared__ int   tot1[NEXP];

    // parallel reduction of per-gate-block partials (tid == gate block id)
    {
        float pme[NEXP]; int pce[NEXP];
        const float4* mp = (const float4*)(g_me_part + tid * NEXP);
        float4 m0 = mp[0], m1 = mp[1];
        pme[0] = m0.x; pme[1] = m0.y; pme[2] = m0.z; pme[3] = m0.w;
        pme[4] = m1.x; pme[5] = m1.y; pme[6] = m1.z; pme[7] = m1.w;
        const int4* cp = (const int4*)(g_ce_part + tid * NEXP);
        int4 c0 = cp[0], c1 = cp[1];
        pce[0] = c0.x; pce[1] = c0.y; pce[2] = c0.z; pce[3] = c0.w;
        pce[4] = c1.x; pce[5] = c1.y; pce[6] = c1.z; pce[7] = c1.w;
#pragma unroll
        for (int o = 16; o > 0; o >>= 1) {
#pragma unroll
            for (int e = 0; e < NEXP; e++) {
                pme[e] += __shfl_down_sync(0xFFFFFFFFu, pme[e], o);
                pce[e] += __shfl_down_sync(0xFFFFFFFFu, pce[e], o);
            }
        }
        if (lane == 0) {
#pragma unroll
            for (int e = 0; e < NEXP; e++) { wred_me[warp][e] = pme[e]; wred_ce[warp][e] = pce[e]; }
        }
    }

    int c1[NEXP], c2[NEXP];
#pragma unroll
    for (int e = 0; e < NEXP; e++) { c1[e] = 0; c2[e] = 0; }
    for (int i = 0; i < PT; i++) {
        int s = tid * PT + i;
        c1[g_e1[s]]++;
        c2[g_e2[s]]++;
    }
#pragma unroll
    for (int e = 0; e < NEXP; e++) { sc1[tid][e] = c1[e]; sc2[tid][e] = c2[e]; }
    __syncthreads();

    if (tid < NEXP) {
        float ms = 0.f; int cs = 0;
#pragma unroll
        for (int w = 0; w < 16; w++) { ms += wred_me[w][tid]; cs += wred_ce[w][tid]; }
        sh_me[tid] = ms; sh_ce[tid] = cs;
    }

    for (int off = 1; off < T; off *= 2) {
        int v1[NEXP], v2[NEXP];
        if (tid >= off) {
#pragma unroll
            for (int e = 0; e < NEXP; e++) { v1[e] = sc1[tid - off][e]; v2[e] = sc2[tid - off][e]; }
        }
        __syncthreads();
        if (tid >= off) {
#pragma unroll
            for (int e = 0; e < NEXP; e++) { sc1[tid][e] += v1[e]; sc2[tid][e] += v2[e]; }
        }
        __syncthreads();
    }
    if (tid < NEXP) tot1[tid] = sc1[T - 1][tid];

    int b1[NEXP], b2[NEXP];
#pragma unroll
    for (int e = 0; e < NEXP; e++) { b1[e] = sc1[tid][e] - c1[e]; b2[e] = sc2[tid][e] - c2[e]; }
    __syncthreads();

    for (int i = 0; i < PT; i++) {
        int s = tid * PT + i;
        int e1 = g_e1[s], e2 = g_e2[s];
        int loc1 = b1[e1]++;
        int loc2 = b2[e2]++ + tot1[e2];
        float p1 = g_p1[s], p2 = g_p2[s];
        bool k1 = (loc1 < CAP), k2 = (loc2 < CAP);
        float gg1 = k1 ? p1 : 0.f, gg2 = k2 ? p2 : 0.f;
        float den = gg1 + gg2;
        den = fmaxf(den, 1.1920929e-07f);
        float w1 = gg1 / den, w2 = gg2 / den;
        if (k1) {
            int sl1 = e1 * CAP + loc1;
            g_slot2tok[sl1] = s;
            g_wslot[sl1] = w1;
        }
        if (k2) {
            int sl2 = e2 * CAP + loc2;
            g_slot2tok[sl2] = s;
            g_wslot[sl2] = w2;
        }
    }

    if (tid == 0 && out_size > S_TOK * MDIM) {
        float la = 0.f;
#pragma unroll
        for (int e = 0; e < NEXP; e++)
            la += (sh_me[e] / (float)S_TOK) * ((float)sh_ce[e] / (float)S_TOK);
        out[(size_t)S_TOK * MDIM] = la * (float)NEXP;
    }
}

// ---------------- fp16 tensor-core GEMM: BK=32, 4-stage, ldmatrix, atomic combine ----------------
// CTA tile 128x128x32, 8 warps (warp tile 32x64), mma.m16n8k16.f16
#define BM 128
#define BN 128
#define BK 32
#define NSTG (MDIM / BK)            // 32
#define NPIPE 4
#define AH 40                       // halves per A smem row (conflict-free for ldmatrix)
#define BH 40                       // halves per B smem row ([n][k] layout)
#define ABUF_H (BM * AH)            // 5120 halves
#define BBUF_H (BN * BH)            // 5120 halves
#define BUFSZ_H (ABUF_H + BBUF_H)   // 10240 halves = 20480 B
#define GEMM_SMEM (NPIPE * BUFSZ_H * 2)   // 81920 bytes

__global__ void __launch_bounds__(256, 2) k_gemm_mma(const __half* __restrict__ Wt,
                                                     const float* __restrict__ bias,
                                                     float* __restrict__ out) {
    extern __shared__ __half smh[];
    int tid = threadIdx.x, wid = tid >> 5, lane = tid & 31;
    int grp = lane >> 2, tg = lane & 3;
    int e = blockIdx.z;
    int row0 = blockIdx.y * BM;
    int col0 = blockIdx.x * BN;
    int wm = (wid & 3) * 32, wn = (wid >> 2) * 64;

    // loaders: each thread = 2 A chunks + 2 B chunks (16B each) per stage
    int arow = tid >> 1, aq = tid & 1;
    int slotbase = e * CAP + row0;
    int t0 = g_slot2tok[slotbase + arow];
    const __half* asrc = g_xh + (size_t)(t0 < 0 ? 0 : t0) * MDIM + aq * 16;
    uint32_t asz = (t0 >= 0) ? 16u : 0u;
    const __half* bsrc = Wt + (size_t)e * MDIM * MDIM + (size_t)(col0 + arow) * MDIM + aq * 16;
    uint32_t s0 = smem_u32(smh);
    uint32_t a_dst_off = (uint32_t)(arow * AH + aq * 16) * 2u;
    uint32_t b_dst_off = (uint32_t)(ABUF_H + arow * BH + aq * 16) * 2u;

    // ldmatrix per-lane source offsets
    uint32_t a_lm[2];
#pragma unroll
    for (int mi = 0; mi < 2; mi++)
        a_lm[mi] = (uint32_t)(((wm + mi * 16 + (lane & 15)) * AH + ((lane >> 4) * 8)) * 2);
    uint32_t b_lm[4];
#pragma unroll
    for (int p = 0; p < 4; p++)
        b_lm[p] = (uint32_t)((ABUF_H + (wn + (2 * p + (lane >> 4)) * 8 + (lane & 7)) * BH
                              + (((lane >> 3) & 1) * 8)) * 2);

    // bias segments for this thread's output columns
    float2 bb[8];
#pragma unroll
    for (int nj = 0; nj < 8; nj++)
        bb[nj] = *(const float2*)(bias + (size_t)e * MDIM + col0 + wn + nj * 8 + tg * 2);

    float d[2][8][4];
#pragma unroll
    for (int mi = 0; mi < 2; mi++)
#pragma unroll
        for (int nj = 0; nj < 8; nj++)
#pragma unroll
            for (int q = 0; q < 4; q++) d[mi][nj][q] = 0.f;

#define LOAD_STAGE(buf, k0) do {                                               \
    uint32_t sb0 = s0 + (uint32_t)((buf) * BUFSZ_H) * 2u;                      \
    CP_ASYNC16Z(sb0 + a_dst_off,       asrc + (k0),     asz);                  \
    CP_ASYNC16Z(sb0 + a_dst_off + 16u, asrc + (k0) + 8, asz);                  \
    CP_ASYNC16(sb0 + b_dst_off,        bsrc + (k0));                           \
    CP_ASYNC16(sb0 + b_dst_off + 16u,  bsrc + (k0) + 8);                       \
} while (0)

    // prologue: prefetch stages 0..2 (3 groups in flight)
#pragma unroll
    for (int p = 0; p < NPIPE - 1; p++) {
        LOAD_STAGE(p, p * BK);
        CP_COMMIT();
    }

    for (int s = 0; s < NSTG; s++) {
        int cur = s % NPIPE;
        CP_WAIT2();                 // group for stage s retired (≤2 pending)
        __syncthreads();            // data visible + prior compute done before overwrite

        uint32_t base = s0 + (uint32_t)(cur * BUFSZ_H) * 2u;
#pragma unroll
        for (int ks = 0; ks < 2; ks++) {
            uint32_t kbyte = (uint32_t)(ks * 16 * 2);
            uint32_t a[2][4];
#pragma unroll
            for (int mi = 0; mi < 2; mi++)
                ldmx4(a[mi][0], a[mi][1], a[mi][2], a[mi][3], base + a_lm[mi] + kbyte);
            uint32_t b[8][2];
#pragma unroll
            for (int p = 0; p < 4; p++)
                ldmx4(b[2 * p][0], b[2 * p][1], b[2 * p + 1][0], b[2 * p + 1][1],
                      base + b_lm[p] + kbyte);
#pragma unroll
            for (int mi = 0; mi < 2; mi++)
#pragma unroll
                for (int nj = 0; nj < 8; nj++)
                    mma_f16(d[mi][nj], a[mi], b[nj]);
        }

        if (s + NPIPE - 1 < NSTG)
            LOAD_STAGE((s + NPIPE - 1) % NPIPE, (s + NPIPE - 1) * BK);
        CP_COMMIT();
    }

    // epilogue: atomic weighted scatter directly into out (combine fused)
    // each thread owns rows (wm+mi*16+grp) and +8, cols wn+nj*8+tg*2 (+1)
#pragma unroll
    for (int mi = 0; mi < 2; mi++) {
#pragma unroll
        for (int half = 0; half < 2; half++) {
            int r = wm + mi * 16 + grp + half * 8;
            int slot = slotbase + r;
            int tok = g_slot2tok[slot];
            if (tok >= 0) {
                float w = g_wslot[slot];
                float* dst = out + (size_t)tok * MDIM + col0 + wn;
#pragma unroll
                for (int nj = 0; nj < 8; nj++) {
                    float v0 = d[mi][nj][2 * half + 0] + bb[nj].x;
                    float v1 = d[mi][nj][2 * half + 1] + bb[nj].y;
                    atomicAdd(dst + nj * 8 + tg * 2,     w * v0);
                    atomicAdd(dst + nj * 8 + tg * 2 + 1, w * v1);
                }
            }
        }
    }
}

// ---------------- launch ----------------
extern "C" void kernel_launch(void* const* d_in, const int* in_sizes, int n_in,
                              void* d_out, int out_size) {
    const float* x  = (const float*)d_in[0];   // [2,2048,1024]
    const float* wg = (const float*)d_in[1];   // [1024,8]
    const float* ew = (const float*)d_in[2];   // [8,1024,1024]
    const float* eb = (const float*)d_in[3];   // [8,1024]
    float* out = (float*)d_out;

    cudaFuncSetAttribute(k_gemm_mma, cudaFuncAttributeMaxDynamicSharedMemorySize, GEMM_SMEM);

    k_gate<<<GATE_BLOCKS, 256>>>(x, wg, out);
    dim3 wt(MDIM / 32, MDIM / 32, NEXP);
    k_wh<<<wt, dim3(32, 8, 1)>>>(ew);
    k_scan<<<1, SCAN_T>>>(out, out_size);
    dim3 gg(MDIM / BN, CAP / BM, NEXP);   // 8 x 8 x 8
    __half* wh_ptr;
    cudaGetSymbolAddress((void**)&wh_ptr, g_wh);
    k_gemm_mma<<<gg, 256, GEMM_SMEM>>>(wh_ptr, eb, out);
}

// round 17
// speedup vs baseline: 1.5810x; 1.0368x over previous
#include <cuda_runtime.h>
#include <cuda_fp16.h>
#include <math.h>
#include <stdint.h>

#define S_TOK 4096
#define MDIM  1024
#define NEXP  8
#define CAP   1024
#define NSLOT (NEXP*CAP)        // 8192
#define GATE_BLOCKS (S_TOK/8)   // 512
#define WH_BLOCKS (32*32*NEXP)  // 8192

// ---------------- device scratch (no allocations allowed) ----------------
__device__ int    g_e1[S_TOK], g_e2[S_TOK];
__device__ float  g_p1[S_TOK], g_p2[S_TOK];
__device__ int    g_slot2tok[NSLOT];
__device__ float  g_wslot[NSLOT];
__device__ float  g_me_part[GATE_BLOCKS*NEXP];
__device__ int    g_ce_part[GATE_BLOCKS*NEXP];
__device__ __half g_xh[(size_t)S_TOK*MDIM];         // 8 MB  (x in fp16)
__device__ __half g_wh[(size_t)NEXP*MDIM*MDIM];     // 16 MB (W transposed [e][n][k] fp16)

// ---------------- helpers ----------------
__device__ __forceinline__ uint32_t smem_u32(const void* p) {
    uint32_t a;
    asm("{ .reg .u64 t; cvta.to.shared.u64 t, %1; cvt.u32.u64 %0, t; }" : "=r"(a) : "l"(p));
    return a;
}
__device__ __forceinline__ void mma_f16(float* d, const uint32_t* a, const uint32_t* b) {
    asm volatile(
        "mma.sync.aligned.m16n8k16.row.col.f32.f16.f16.f32 "
        "{%0,%1,%2,%3}, {%4,%5,%6,%7}, {%8,%9}, {%0,%1,%2,%3};"
        : "+f"(d[0]), "+f"(d[1]), "+f"(d[2]), "+f"(d[3])
        : "r"(a[0]), "r"(a[1]), "r"(a[2]), "r"(a[3]), "r"(b[0]), "r"(b[1]));
}
__device__ __forceinline__ void ldmx4(uint32_t& r0, uint32_t& r1, uint32_t& r2, uint32_t& r3,
                                      uint32_t addr) {
    asm volatile("ldmatrix.sync.aligned.m8n8.x4.shared.b16 {%0,%1,%2,%3}, [%4];"
        : "=r"(r0), "=r"(r1), "=r"(r2), "=r"(r3) : "r"(addr));
}
#define CP_ASYNC16(dst, src) \
    asm volatile("cp.async.cg.shared.global [%0], [%1], 16;" :: "r"(dst), "l"(src))
#define CP_ASYNC16Z(dst, src, sz) \
    asm volatile("cp.async.cg.shared.global [%0], [%1], 16, %2;" :: "r"(dst), "l"(src), "r"(sz))
#define CP_COMMIT() asm volatile("cp.async.commit_group;" ::: "memory")
#define CP_WAIT2()  asm volatile("cp.async.wait_group 2;" ::: "memory")

// ---------------- fused gating + W-prep kernel ----------------
// blocks [0, GATE_BLOCKS): gating (+ slot-map init + x->fp16 + out zeroing)
// blocks [GATE_BLOCKS, GATE_BLOCKS+WH_BLOCKS): W transpose + fp16 convert
__global__ void k_gate_wh(const float* __restrict__ x, const float* __restrict__ wg,
                          const float* __restrict__ W, float* __restrict__ out) {
    __shared__ float sh_mem[32 * 33];   // wh transpose tile; gate reuses a slice

    if (blockIdx.x >= GATE_BLOCKS) {
        // ---- W transpose part: [e][k][n] -> [e][n][k] fp16, 32x32 tile ----
        int flat = blockIdx.x - GATE_BLOCKS;
        int e = flat >> 10;              // 1024 tiles per expert
        int rest = flat & 1023;
        int n0 = (rest & 31) * 32;
        int k0 = (rest >> 5) * 32;
        const float* src = W + (size_t)e * MDIM * MDIM;
        __half* dst = g_wh + (size_t)e * MDIM * MDIM;
        int tx = threadIdx.x & 31, ty = threadIdx.x >> 5;   // 32 x 8
        float (*t)[33] = (float(*)[33])sh_mem;
#pragma unroll
        for (int i = 0; i < 32; i += 8)
            t[ty + i][tx] = src[(size_t)(k0 + ty + i) * MDIM + n0 + tx];
        __syncthreads();
#pragma unroll
        for (int i = 0; i < 32; i += 8)
            dst[(size_t)(n0 + ty + i) * MDIM + k0 + tx] = __float2half_rn(t[tx][ty + i]);
        return;
    }

    // ---- gating part ----
    if (threadIdx.x < 16) g_slot2tok[blockIdx.x * 16 + threadIdx.x] = -1;
    // zero out[0 .. S_TOK*MDIM): 512 blocks x 2048 float4
    {
        float4* oz = (float4*)out + (size_t)blockIdx.x * 2048;
#pragma unroll
        for (int i = 0; i < 8; i++)
            oz[threadIdx.x + i * 256] = make_float4(0.f, 0.f, 0.f, 0.f);
    }

    int warp = threadIdx.x >> 5, lane = threadIdx.x & 31;
    int s = blockIdx.x * 8 + warp;

    float acc[NEXP];
#pragma unroll
    for (int e = 0; e < NEXP; e++) acc[e] = 0.f;

    const float* xr = x + (size_t)s * MDIM;
    __half* xh = g_xh + (size_t)s * MDIM;
    for (int m = lane; m < MDIM; m += 32) {
        float xv = xr[m];
        xh[m] = __float2half_rn(xv);
        const float4* w4 = (const float4*)(wg + (size_t)m * NEXP);
        float4 w0 = w4[0], w1 = w4[1];
        acc[0] += xv * w0.x; acc[1] += xv * w0.y;
        acc[2] += xv * w0.z; acc[3] += xv * w0.w;
        acc[4] += xv * w1.x; acc[5] += xv * w1.y;
        acc[6] += xv * w1.z; acc[7] += xv * w1.w;
    }
#pragma unroll
    for (int o = 16; o > 0; o >>= 1) {
#pragma unroll
        for (int e = 0; e < NEXP; e++)
            acc[e] += __shfl_down_sync(0xFFFFFFFFu, acc[e], o);
    }

    float* sh_g = sh_mem;                 // [8][NEXP]
    int*   sh_e1 = (int*)(sh_mem + 64);   // [8]

    if (lane == 0) {
        float mx = acc[0];
#pragma unroll
        for (int e = 1; e < NEXP; e++) mx = fmaxf(mx, acc[e]);
        float ex[NEXP]; float sum = 0.f;
#pragma unroll
        for (int e = 0; e < NEXP; e++) { ex[e] = expf(acc[e] - mx); sum += ex[e]; }
        float inv = 1.f / sum;

        int e1 = 0; float b1 = acc[0];
#pragma unroll
        for (int e = 1; e < NEXP; e++) if (acc[e] > b1) { b1 = acc[e]; e1 = e; }
        int e2 = -1; float b2 = -3.4e38f;
#pragma unroll
        for (int e = 0; e < NEXP; e++) if (e != e1 && acc[e] > b2) { b2 = acc[e]; e2 = e; }

        float p1 = 0.f, p2 = 0.f;
#pragma unroll
        for (int e = 0; e < NEXP; e++) {
            float ge = ex[e] * inv;
            if (e == e1) p1 = ge;
            if (e == e2) p2 = ge;
            sh_g[warp * NEXP + e] = ge;
        }
        g_e1[s] = e1; g_e2[s] = e2;
        g_p1[s] = p1; g_p2[s] = p2;
        sh_e1[warp] = e1;
    }
    __syncthreads();

    if (threadIdx.x < NEXP) {
        int e = threadIdx.x;
        float ms = 0.f; int cs = 0;
#pragma unroll
        for (int w = 0; w < 8; w++) { ms += sh_g[w * NEXP + e]; cs += (sh_e1[w] == e); }
        g_me_part[blockIdx.x * NEXP + e] = ms;
        g_ce_part[blockIdx.x * NEXP + e] = cs;
    }
}

// ---------------- scan (512 threads, parallel partial reduction) ----------------
#define SCAN_T 512
__global__ void k_scan(float* __restrict__ out, int out_size) {
    const int T = SCAN_T, PT = S_TOK / T;   // 8 tokens per thread
    int tid = threadIdx.x;
    int lane = tid & 31, warp = tid >> 5;   // 16 warps

    __shared__ int   sc1[T][NEXP], sc2[T][NEXP];
    __shared__ float wred_me[16][NEXP];
    __shared__ int   wred_ce[16][NEXP];
    __shared__ float sh_me[NEXP];
    __shared__ int   sh_ce[NEXP];
    __shared__ int   tot1[NEXP];

    // parallel reduction of per-gate-block partials (tid == gate block id)
    {
        float pme[NEXP]; int pce[NEXP];
        const float4* mp = (const float4*)(g_me_part + tid * NEXP);
        float4 m0 = mp[0], m1 = mp[1];
        pme[0] = m0.x; pme[1] = m0.y; pme[2] = m0.z; pme[3] = m0.w;
        pme[4] = m1.x; pme[5] = m1.y; pme[6] = m1.z; pme[7] = m1.w;
        const int4* cp = (const int4*)(g_ce_part + tid * NEXP);
        int4 c0 = cp[0], c1 = cp[1];
        pce[0] = c0.x; pce[1] = c0.y; pce[2] = c0.z; pce[3] = c0.w;
        pce[4] = c1.x; pce[5] = c1.y; pce[6] = c1.z; pce[7] = c1.w;
#pragma unroll
        for (int o = 16; o > 0; o >>= 1) {
#pragma unroll
            for (int e = 0; e < NEXP; e++) {
                pme[e] += __shfl_down_sync(0xFFFFFFFFu, pme[e], o);
                pce[e] += __shfl_down_sync(0xFFFFFFFFu, pce[e], o);
            }
        }
        if (lane == 0) {
#pragma unroll
            for (int e = 0; e < NEXP; e++) { wred_me[warp][e] = pme[e]; wred_ce[warp][e] = pce[e]; }
        }
    }

    int c1[NEXP], c2[NEXP];
#pragma unroll
    for (int e = 0; e < NEXP; e++) { c1[e] = 0; c2[e] = 0; }
    for (int i = 0; i < PT; i++) {
        int s = tid * PT + i;
        c1[g_e1[s]]++;
        c2[g_e2[s]]++;
    }
#pragma unroll
    for (int e = 0; e < NEXP; e++) { sc1[tid][e] = c1[e]; sc2[tid][e] = c2[e]; }
    __syncthreads();

    if (tid < NEXP) {
        float ms = 0.f; int cs = 0;
#pragma unroll
        for (int w = 0; w < 16; w++) { ms += wred_me[w][tid]; cs += wred_ce[w][tid]; }
        sh_me[tid] = ms; sh_ce[tid] = cs;
    }

    for (int off = 1; off < T; off *= 2) {
        int v1[NEXP], v2[NEXP];
        if (tid >= off) {
#pragma unroll
            for (int e = 0; e < NEXP; e++) { v1[e] = sc1[tid - off][e]; v2[e] = sc2[tid - off][e]; }
        }
        __syncthreads();
        if (tid >= off) {
#pragma unroll
            for (int e = 0; e < NEXP; e++) { sc1[tid][e] += v1[e]; sc2[tid][e] += v2[e]; }
        }
        __syncthreads();
    }
    if (tid < NEXP) tot1[tid] = sc1[T - 1][tid];

    int b1[NEXP], b2[NEXP];
#pragma unroll
    for (int e = 0; e < NEXP; e++) { b1[e] = sc1[tid][e] - c1[e]; b2[e] = sc2[tid][e] - c2[e]; }
    __syncthreads();

    for (int i = 0; i < PT; i++) {
        int s = tid * PT + i;
        int e1 = g_e1[s], e2 = g_e2[s];
        int loc1 = b1[e1]++;
        int loc2 = b2[e2]++ + tot1[e2];
        float p1 = g_p1[s], p2 = g_p2[s];
        bool k1 = (loc1 < CAP), k2 = (loc2 < CAP);
        float gg1 = k1 ? p1 : 0.f, gg2 = k2 ? p2 : 0.f;
        float den = gg1 + gg2;
        den = fmaxf(den, 1.1920929e-07f);
        float w1 = gg1 / den, w2 = gg2 / den;
        if (k1) {
            int sl1 = e1 * CAP + loc1;
            g_slot2tok[sl1] = s;
            g_wslot[sl1] = w1;
        }
        if (k2) {
            int sl2 = e2 * CAP + loc2;
            g_slot2tok[sl2] = s;
            g_wslot[sl2] = w2;
        }
    }

    if (tid == 0 && out_size > S_TOK * MDIM) {
        float la = 0.f;
#pragma unroll
        for (int e = 0; e < NEXP; e++)
            la += (sh_me[e] / (float)S_TOK) * ((float)sh_ce[e] / (float)S_TOK);
        out[(size_t)S_TOK * MDIM] = la * (float)NEXP;
    }
}

// ---------------- fp16 tensor-core GEMM: BK=32, 4-stage, ldmatrix, atomic combine ----------------
// CTA tile 128x128x32, 8 warps (warp tile 32x64), mma.m16n8k16.f16
#define BM 128
#define BN 128
#define BK 32
#define NSTG (MDIM / BK)            // 32
#define NPIPE 4
#define AH 40                       // halves per A smem row (conflict-free for ldmatrix)
#define BH 40                       // halves per B smem row ([n][k] layout)
#define ABUF_H (BM * AH)            // 5120 halves
#define BBUF_H (BN * BH)            // 5120 halves
#define BUFSZ_H (ABUF_H + BBUF_H)   // 10240 halves = 20480 B
#define GEMM_SMEM (NPIPE * BUFSZ_H * 2)   // 81920 bytes

__global__ void __launch_bounds__(256, 2) k_gemm_mma(const __half* __restrict__ Wt,
                                                     const float* __restrict__ bias,
                                                     float* __restrict__ out) {
    extern __shared__ __half smh[];
    int tid = threadIdx.x, wid = tid >> 5, lane = tid & 31;
    int grp = lane >> 2, tg = lane & 3;
    int e = blockIdx.z;
    int row0 = blockIdx.y * BM;
    int col0 = blockIdx.x * BN;
    int wm = (wid & 3) * 32, wn = (wid >> 2) * 64;

    // loaders: each thread = 2 A chunks + 2 B chunks (16B each) per stage
    int arow = tid >> 1, aq = tid & 1;
    int slotbase = e * CAP + row0;
    int t0 = g_slot2tok[slotbase + arow];
    const __half* asrc = g_xh + (size_t)(t0 < 0 ? 0 : t0) * MDIM + aq * 16;
    uint32_t asz = (t0 >= 0) ? 16u : 0u;
    const __half* bsrc = Wt + (size_t)e * MDIM * MDIM + (size_t)(col0 + arow) * MDIM + aq * 16;
    uint32_t s0 = smem_u32(smh);
    uint32_t a_dst_off = (uint32_t)(arow * AH + aq * 16) * 2u;
    uint32_t b_dst_off = (uint32_t)(ABUF_H + arow * BH + aq * 16) * 2u;

    // ldmatrix per-lane source offsets
    uint32_t a_lm[2];
#pragma unroll
    for (int mi = 0; mi < 2; mi++)
        a_lm[mi] = (uint32_t)(((wm + mi * 16 + (lane & 15)) * AH + ((lane >> 4) * 8)) * 2);
    uint32_t b_lm[4];
#pragma unroll
    for (int p = 0; p < 4; p++)
        b_lm[p] = (uint32_t)((ABUF_H + (wn + (2 * p + (lane >> 4)) * 8 + (lane & 7)) * BH
                              + (((lane >> 3) & 1) * 8)) * 2);

    // bias segments for this thread's output columns
    float2 bb[8];
#pragma unroll
    for (int nj = 0; nj < 8; nj++)
        bb[nj] = *(const float2*)(bias + (size_t)e * MDIM + col0 + wn + nj * 8 + tg * 2);

    float d[2][8][4];
#pragma unroll
    for (int mi = 0; mi < 2; mi++)
#pragma unroll
        for (int nj = 0; nj < 8; nj++)
#pragma unroll
            for (int q = 0; q < 4; q++) d[mi][nj][q] = 0.f;

#define LOAD_STAGE(buf, k0) do {                                               \
    uint32_t sb0 = s0 + (uint32_t)((buf) * BUFSZ_H) * 2u;                      \
    CP_ASYNC16Z(sb0 + a_dst_off,       asrc + (k0),     asz);                  \
    CP_ASYNC16Z(sb0 + a_dst_off + 16u, asrc + (k0) + 8, asz);                  \
    CP_ASYNC16(sb0 + b_dst_off,        bsrc + (k0));                           \
    CP_ASYNC16(sb0 + b_dst_off + 16u,  bsrc + (k0) + 8);                       \
} while (0)

    // prologue: prefetch stages 0..2 (3 groups in flight)
#pragma unroll
    for (int p = 0; p < NPIPE - 1; p++) {
        LOAD_STAGE(p, p * BK);
        CP_COMMIT();
    }

    for (int s = 0; s < NSTG; s++) {
        int cur = s % NPIPE;
        CP_WAIT2();                 // group for stage s retired (≤2 pending)
        __syncthreads();            // data visible + prior compute done before overwrite

        uint32_t base = s0 + (uint32_t)(cur * BUFSZ_H) * 2u;
#pragma unroll
        for (int ks = 0; ks < 2; ks++) {
            uint32_t kbyte = (uint32_t)(ks * 16 * 2);
            uint32_t a[2][4];
#pragma unroll
            for (int mi = 0; mi < 2; mi++)
                ldmx4(a[mi][0], a[mi][1], a[mi][2], a[mi][3], base + a_lm[mi] + kbyte);
            uint32_t b[8][2];
#pragma unroll
            for (int p = 0; p < 4; p++)
                ldmx4(b[2 * p][0], b[2 * p][1], b[2 * p + 1][0], b[2 * p + 1][1],
                      base + b_lm[p] + kbyte);
#pragma unroll
            for (int mi = 0; mi < 2; mi++)
#pragma unroll
                for (int nj = 0; nj < 8; nj++)
                    mma_f16(d[mi][nj], a[mi], b[nj]);
        }

        if (s + NPIPE - 1 < NSTG)
            LOAD_STAGE((s + NPIPE - 1) % NPIPE, (s + NPIPE - 1) * BK);
        CP_COMMIT();
    }

    // epilogue: atomic weighted scatter directly into out (combine fused)
#pragma unroll
    for (int mi = 0; mi < 2; mi++) {
#pragma unroll
        for (int half = 0; half < 2; half++) {
            int r = wm + mi * 16 + grp + half * 8;
            int slot = slotbase + r;
            int tok = g_slot2tok[slot];
            if (tok >= 0) {
                float w = g_wslot[slot];
                float* dst = out + (size_t)tok * MDIM + col0 + wn;
#pragma unroll
                for (int nj = 0; nj < 8; nj++) {
                    float v0 = d[mi][nj][2 * half + 0] + bb[nj].x;
                    float v1 = d[mi][nj][2 * half + 1] + bb[nj].y;
                    atomicAdd(dst + nj * 8 + tg * 2,     w * v0);
                    atomicAdd(dst + nj * 8 + tg * 2 + 1, w * v1);
                }
            }
        }
    }
}

// ---------------- launch ----------------
extern "C" void kernel_launch(void* const* d_in, const int* in_sizes, int n_in,
                              void* d_out, int out_size) {
    const float* x  = (const float*)d_in[0];   // [2,2048,1024]
    const float* wg = (const float*)d_in[1];   // [1024,8]
    const float* ew = (const float*)d_in[2];   // [8,1024,1024]
    const float* eb = (const float*)d_in[3];   // [8,1024]
    float* out = (float*)d_out;

    cudaFuncSetAttribute(k_gemm_mma, cudaFuncAttributeMaxDynamicSharedMemorySize, GEMM_SMEM);

    k_gate_wh<<<GATE_BLOCKS + WH_BLOCKS, 256>>>(x, wg, ew, out);
    k_scan<<<1, SCAN_T>>>(out, out_size);
    dim3 gg(MDIM / BN, CAP / BM, NEXP);   // 8 x 8 x 8
    __half* wh_ptr;
    cudaGetSymbolAddress((void**)&wh_ptr, g_wh);
    k_gemm_mma<<<gg, 256, GEMM_SMEM>>>(wh_ptr, eb, out);
}